// round 1
// baseline (speedup 1.0000x reference)
#include <cuda_runtime.h>
#include <cstddef>

#define NKP 21
#define CH 32
#define BB_ 8
#define HH 96
#define WW 96
#define HWPIX (HH*WW)          /* 9216 */

#define TILE_W 32
#define TILE_H 16
#define HALO_W (TILE_W+2)      /* 34 */
#define HALO_H (TILE_H+2)      /* 18 */
#define HALO_N (HALO_W*HALO_H) /* 612 */

/* scratch: f in [b][c][y][x] layout + per-pixel channel-sum of f */
__device__ float g_f[BB_*CH*HWPIX];
__device__ float g_fsum[BB_*HWPIX];

/* ------------------------------------------------------------------ */
/* Kernel 1: f = relu(x @ w2 + b2), stored CHW; fsum = f.sum(ch)       */
/* ------------------------------------------------------------------ */
__global__ void __launch_bounds__(256)
k1_f(const float* __restrict__ x, const float* __restrict__ w2,
     const float* __restrict__ b2)
{
    __shared__ float w2s[CH*CH];
    __shared__ float b2s[CH];
    int tid = threadIdx.x;
    for (int i = tid; i < CH*CH; i += 256) w2s[i] = w2[i];
    if (tid < CH) b2s[tid] = b2[tid];
    __syncthreads();

    int p = blockIdx.x * 256 + tid;          /* pixel in [0, B*HW) — exact grid */

    float xv[CH];
    const float4* xp = (const float4*)(x + (size_t)p * CH);
#pragma unroll
    for (int i = 0; i < CH/4; i++) {
        float4 v = xp[i];
        xv[4*i+0] = v.x; xv[4*i+1] = v.y; xv[4*i+2] = v.z; xv[4*i+3] = v.w;
    }

    float acc[CH];
#pragma unroll
    for (int d = 0; d < CH; d++) acc[d] = b2s[d];
#pragma unroll 4
    for (int c = 0; c < CH; c++) {
        float v = xv[c];
#pragma unroll
        for (int d = 0; d < CH; d++) acc[d] += v * w2s[c*CH + d];
    }

    int b   = p / HWPIX;
    int pix = p % HWPIX;
    float s = 0.f;
#pragma unroll
    for (int d = 0; d < CH; d++) {
        float fv = fmaxf(acc[d], 0.f);
        g_f[(size_t)(b*CH + d) * HWPIX + pix] = fv;   /* coalesced per d */
        s += fv;
    }
    g_fsum[p] = s;
}

/* ------------------------------------------------------------------ */
/* Kernel 2: per (keypoint n, batch b, 32x16 tile)                     */
/*   stage A: h = relu(f @ wa[n] + ba[n]) over halo -> smem [c][y][x]  */
/*   stage B: g = relu(conv3x3(h, wb[n]) + bb[n]);                     */
/*            out = fsum + sum_d g_d * wpsum[n,d]                      */
/* ------------------------------------------------------------------ */
__global__ void __launch_bounds__(256, 1)
k2_main(const float* __restrict__ wa, const float* __restrict__ ba,
        const float* __restrict__ wb, const float* __restrict__ bb,
        const float* __restrict__ Wp, float* __restrict__ out)
{
    extern __shared__ float sm[];
    float* h_s  = sm;                        /* [CH][HALO_H][HALO_W] 19584 */
    float* wb_s = h_s  + CH*HALO_N;          /* [9][CH][CH]           9216 */
    float* wa_s = wb_s + 9*CH*CH;            /* [CH][CH]              1024 */
    float* wp_s = wa_s + CH*CH;              /* [CH] */
    float* ba_s = wp_s + CH;
    float* bb_s = ba_s + CH;

    int tid = threadIdx.x;
    int n = blockIdx.z / BB_;
    int b = blockIdx.z % BB_;
    int tx0 = blockIdx.x * TILE_W;
    int ty0 = blockIdx.y * TILE_H;

    /* stage weights into smem */
    for (int i = tid; i < 9*CH*CH; i += 256)
        wb_s[i] = wb[(size_t)n*9*CH*CH + i];
    for (int i = tid; i < CH*CH; i += 256)
        wa_s[i] = wa[n*CH*CH + i];
    if (tid < CH) {
        float s = 0.f;
        const float* wpp = Wp + (n*CH + tid)*CH;
#pragma unroll
        for (int o = 0; o < CH; o++) s += wpp[o];
        wp_s[tid] = s;                       /* Wp.sum(-1) */
        ba_s[tid] = ba[n*CH + tid];
        bb_s[tid] = bb[n*CH + tid];
    }
    __syncthreads();

    /* ---- stage A: h over halo (zero outside image = SAME padding) ---- */
    for (int hp = tid; hp < HALO_N; hp += 256) {
        int hy = hp / HALO_W, hx = hp % HALO_W;
        int gy = ty0 + hy - 1, gx = tx0 + hx - 1;
        bool ok = (gy >= 0) && (gy < HH) && (gx >= 0) && (gx < WW);
        if (ok) {
            const float* fp = g_f + (size_t)b*CH*HWPIX + gy*WW + gx;
            float fv[CH];
#pragma unroll
            for (int e = 0; e < CH; e++) fv[e] = fp[(size_t)e * HWPIX];
            float acc[CH];
#pragma unroll
            for (int d = 0; d < CH; d++) acc[d] = ba_s[d];
#pragma unroll 4
            for (int e = 0; e < CH; e++) {
                float v = fv[e];
#pragma unroll
                for (int d = 0; d < CH; d++) acc[d] += v * wa_s[e*CH + d];
            }
#pragma unroll
            for (int d = 0; d < CH; d++)
                h_s[d*HALO_N + hp] = fmaxf(acc[d], 0.f);
        } else {
#pragma unroll
            for (int d = 0; d < CH; d++) h_s[d*HALO_N + hp] = 0.f;
        }
    }
    __syncthreads();

    /* ---- stage B: 3x3 conv, 2 output pixels per thread (y0, y0+8) ---- */
    int x  = tid & 31;
    int y0 = tid >> 5;                       /* 0..7 */

    float acc0[CH], acc1[CH];
#pragma unroll
    for (int d = 0; d < CH; d++) { acc0[d] = 0.f; acc1[d] = 0.f; }

#pragma unroll 1
    for (int t = 0; t < 9; t++) {
        int ky = t / 3, kx = t - 3*ky;
        const float* hr0 = h_s + (y0 + ky) * HALO_W + (x + kx);
        const float* hr1 = hr0 + 8 * HALO_W;
        const float* wr  = wb_s + t * CH * CH;
#pragma unroll 4
        for (int c = 0; c < CH; c++) {
            float hv0 = hr0[c * HALO_N];
            float hv1 = hr1[c * HALO_N];
#pragma unroll
            for (int d = 0; d < CH; d++) {
                float w = wr[c*CH + d];
                acc0[d] += hv0 * w;
                acc1[d] += hv1 * w;
            }
        }
    }

    float l0 = 0.f, l1 = 0.f;
#pragma unroll
    for (int d = 0; d < CH; d++) {
        l0 += fmaxf(acc0[d] + bb_s[d], 0.f) * wp_s[d];
        l1 += fmaxf(acc1[d] + bb_s[d], 0.f) * wp_s[d];
    }

    int gx  = tx0 + x;
    int gy0 = ty0 + y0;
    int gy1 = gy0 + 8;
    float fs0 = g_fsum[b*HWPIX + gy0*WW + gx];
    float fs1 = g_fsum[b*HWPIX + gy1*WW + gx];
    out[((size_t)(b*HH + gy0)*WW + gx)*NKP + n] = fs0 + l0;
    out[((size_t)(b*HH + gy1)*WW + gx)*NKP + n] = fs1 + l1;
}

/* ------------------------------------------------------------------ */
extern "C" void kernel_launch(void* const* d_in, const int* in_sizes, int n_in,
                              void* d_out, int out_size)
{
    const float* x  = (const float*)d_in[0];
    const float* w2 = (const float*)d_in[1];
    const float* b2 = (const float*)d_in[2];
    const float* wa = (const float*)d_in[3];
    const float* ba = (const float*)d_in[4];
    const float* wb = (const float*)d_in[5];
    const float* bb = (const float*)d_in[6];
    const float* Wp = (const float*)d_in[7];
    float* out = (float*)d_out;

    k1_f<<<(BB_*HWPIX)/256, 256>>>(x, w2, b2);

    const int smem_bytes = (CH*HALO_N + 9*CH*CH + CH*CH + 3*CH) * (int)sizeof(float);
    cudaFuncSetAttribute(k2_main, cudaFuncAttributeMaxDynamicSharedMemorySize, smem_bytes);
    dim3 grid(WW/TILE_W, HH/TILE_H, NKP*BB_);
    k2_main<<<grid, 256, smem_bytes>>>(wa, ba, wb, bb, Wp, out);
}

// round 5
// speedup vs baseline: 1.1109x; 1.1109x over previous
#include <cuda_runtime.h>
#include <cstdint>
#include <cstddef>

#define NKP 21
#define CH 32
#define BB_ 8
#define HH 96
#define WW 96
#define HWPIX (HH*WW)          /* 9216 */

#define TILE_W 32
#define TILE_H 16
#define HALO_W (TILE_W+2)      /* 34 */
#define HALO_H (TILE_H+2)      /* 18 */
#define HALO_N (HALO_W*HALO_H) /* 612 */

/* scratch: f in [b][c][y][x] layout + per-pixel channel-sum of f */
__device__ float g_f[BB_*CH*HWPIX];
__device__ float g_fsum[BB_*HWPIX];

/* ---- packed f32x2 helpers (sm_100+) ---- */
__device__ __forceinline__ uint64_t pack2(float v) {
    uint64_t r; asm("mov.b64 %0, {%1, %1};" : "=l"(r) : "f"(v)); return r;
}
__device__ __forceinline__ void ffma2(uint64_t& d, uint64_t a, uint64_t b) {
    asm("fma.rn.f32x2 %0, %1, %2, %0;" : "+l"(d) : "l"(a), "l"(b));
}
__device__ __forceinline__ float2 unpack2(uint64_t v) {
    float2 f; asm("mov.b64 {%0, %1}, %2;" : "=f"(f.x), "=f"(f.y) : "l"(v)); return f;
}

/* ------------------------------------------------------------------ */
/* Kernel 1: f = relu(x @ w2 + b2), stored CHW; fsum = f.sum(ch)       */
/* ------------------------------------------------------------------ */
__global__ void __launch_bounds__(256)
k1_f(const float* __restrict__ x, const float* __restrict__ w2,
     const float* __restrict__ b2)
{
    __shared__ float w2s[CH*CH];
    __shared__ float b2s[CH];
    int tid = threadIdx.x;
    for (int i = tid; i < CH*CH; i += 256) w2s[i] = w2[i];
    if (tid < CH) b2s[tid] = b2[tid];
    __syncthreads();

    int p = blockIdx.x * 256 + tid;          /* pixel in [0, B*HW) — exact grid */

    uint64_t acc[CH/2];
    const uint64_t* b2p = (const uint64_t*)b2s;
#pragma unroll
    for (int j = 0; j < CH/2; j++) acc[j] = b2p[j];

    const float4* xp = (const float4*)(x + (size_t)p * CH);
    const ulonglong2* w2v = (const ulonglong2*)w2s;   /* row = 8 ulonglong2 */
#pragma unroll 2
    for (int c4 = 0; c4 < CH/4; c4++) {
        float4 v = xp[c4];
        float vv[4] = {v.x, v.y, v.z, v.w};
#pragma unroll
        for (int k = 0; k < 4; k++) {
            int c = c4*4 + k;
            uint64_t hv = pack2(vv[k]);
#pragma unroll
            for (int j = 0; j < 8; j++) {
                ulonglong2 w = w2v[c*8 + j];          /* ch 4j..4j+3 */
                ffma2(acc[2*j+0], hv, w.x);
                ffma2(acc[2*j+1], hv, w.y);
            }
        }
    }

    int b   = p / HWPIX;
    int pix = p % HWPIX;
    float s = 0.f;
#pragma unroll
    for (int j = 0; j < CH/2; j++) {
        float2 a = unpack2(acc[j]);
        float f0 = fmaxf(a.x, 0.f);
        float f1 = fmaxf(a.y, 0.f);
        g_f[(size_t)(b*CH + 2*j+0) * HWPIX + pix] = f0;
        g_f[(size_t)(b*CH + 2*j+1) * HWPIX + pix] = f1;
        s += f0 + f1;
    }
    g_fsum[p] = s;
}

/* ------------------------------------------------------------------ */
/* Kernel 2: per (keypoint n, batch b, 32x16 tile)                     */
/*   stage A: h = relu(f @ wa[n] + ba[n]) over halo -> smem [c][y][x]  */
/*   stage B: g = relu(conv3x3(h, wb[n]) + bb[n]);                     */
/*            out = fsum + sum_d g_d * wpsum[n,d]                      */
/*   2 output pixels per thread (rows y0, y0+8)                        */
/* ------------------------------------------------------------------ */
__global__ void __launch_bounds__(256, 1)
k2_main(const float* __restrict__ wa, const float* __restrict__ ba,
        const float* __restrict__ wb, const float* __restrict__ bb,
        const float* __restrict__ Wp, float* __restrict__ out)
{
    extern __shared__ float sm[];
    float* h_s  = sm;                        /* [CH][HALO_H][HALO_W] 78336 B */
    float* wb_s = h_s  + CH*HALO_N;          /* [9][CH][CH]          36864 B */
    float* wa_s = wb_s + 9*CH*CH;            /* [CH][CH]              4096 B */
    float* wp_s = wa_s + CH*CH;              /* [CH] */
    float* ba_s = wp_s + CH;
    float* bb_s = ba_s + CH;

    int tid = threadIdx.x;
    int n = blockIdx.z / BB_;
    int b = blockIdx.z % BB_;
    int tx0 = blockIdx.x * TILE_W;
    int ty0 = blockIdx.y * TILE_H;

    /* stage weights into smem */
    for (int i = tid; i < 9*CH*CH; i += 256)
        wb_s[i] = wb[(size_t)n*9*CH*CH + i];
    for (int i = tid; i < CH*CH; i += 256)
        wa_s[i] = wa[n*CH*CH + i];
    if (tid < CH) {
        float s = 0.f;
        const float* wpp = Wp + (n*CH + tid)*CH;
#pragma unroll
        for (int o = 0; o < CH; o++) s += wpp[o];
        wp_s[tid] = s;                       /* Wp.sum(-1) */
        ba_s[tid] = ba[n*CH + tid];
        bb_s[tid] = bb[n*CH + tid];
    }
    __syncthreads();

    /* ---- stage A: h over halo (zero outside image = SAME padding) ---- */
    const ulonglong2* wav = (const ulonglong2*)wa_s;
    for (int hp = tid; hp < HALO_N; hp += 256) {
        int hy = hp / HALO_W, hx = hp % HALO_W;
        int gy = ty0 + hy - 1, gx = tx0 + hx - 1;
        bool ok = (gy >= 0) && (gy < HH) && (gx >= 0) && (gx < WW);
        if (ok) {
            const float* fp = g_f + (size_t)b*CH*HWPIX + gy*WW + gx;
            float fv[CH];
#pragma unroll
            for (int e = 0; e < CH; e++) fv[e] = fp[(size_t)e * HWPIX];

            uint64_t acc[CH/2];
            const uint64_t* bap = (const uint64_t*)ba_s;
#pragma unroll
            for (int j = 0; j < CH/2; j++) acc[j] = bap[j];

#pragma unroll 2
            for (int e = 0; e < CH; e++) {
                uint64_t hv = pack2(fv[e]);
#pragma unroll
                for (int j = 0; j < 8; j++) {
                    ulonglong2 w = wav[e*8 + j];
                    ffma2(acc[2*j+0], hv, w.x);
                    ffma2(acc[2*j+1], hv, w.y);
                }
            }
#pragma unroll
            for (int j = 0; j < CH/2; j++) {
                float2 a = unpack2(acc[j]);
                h_s[(2*j+0)*HALO_N + hp] = fmaxf(a.x, 0.f);
                h_s[(2*j+1)*HALO_N + hp] = fmaxf(a.y, 0.f);
            }
        } else {
#pragma unroll
            for (int d = 0; d < CH; d++) h_s[d*HALO_N + hp] = 0.f;
        }
    }
    __syncthreads();

    /* ---- stage B: 3x3 conv, 2 output pixels per thread ---- */
    int x  = tid & 31;
    int y0 = tid >> 5;                       /* 0..7 */

    uint64_t acc0[CH/2], acc1[CH/2];
#pragma unroll
    for (int j = 0; j < CH/2; j++) { acc0[j] = 0ull; acc1[j] = 0ull; }

#pragma unroll 1
    for (int t = 0; t < 9; t++) {
        int ky = t / 3, kx = t - 3*ky;
        const float* hr = h_s + (y0 + ky) * HALO_W + (x + kx);
        const ulonglong2* wr = (const ulonglong2*)(wb_s + t * CH * CH);
#pragma unroll 2
        for (int c = 0; c < CH; c++) {
            const float* hc = hr + c * HALO_N;
            uint64_t hp0 = pack2(hc[0]);
            uint64_t hp1 = pack2(hc[8*HALO_W]);
#pragma unroll
            for (int j = 0; j < 8; j++) {
                ulonglong2 w = wr[c*8 + j];
                ffma2(acc0[2*j+0], hp0, w.x);
                ffma2(acc0[2*j+1], hp0, w.y);
                ffma2(acc1[2*j+0], hp1, w.x);
                ffma2(acc1[2*j+1], hp1, w.y);
            }
        }
    }

    int gx = tx0 + x;
    float l0 = 0.f, l1 = 0.f;
#pragma unroll
    for (int j = 0; j < CH/2; j++) {
        float2 a0 = unpack2(acc0[j]);
        float2 a1 = unpack2(acc1[j]);
        l0 += fmaxf(a0.x + bb_s[2*j+0], 0.f) * wp_s[2*j+0];
        l0 += fmaxf(a0.y + bb_s[2*j+1], 0.f) * wp_s[2*j+1];
        l1 += fmaxf(a1.x + bb_s[2*j+0], 0.f) * wp_s[2*j+0];
        l1 += fmaxf(a1.y + bb_s[2*j+1], 0.f) * wp_s[2*j+1];
    }

    int gy0 = ty0 + y0;
    int gy1 = gy0 + 8;
    float fs0 = g_fsum[b*HWPIX + gy0*WW + gx];
    float fs1 = g_fsum[b*HWPIX + gy1*WW + gx];
    out[((size_t)(b*HH + gy0)*WW + gx)*NKP + n] = fs0 + l0;
    out[((size_t)(b*HH + gy1)*WW + gx)*NKP + n] = fs1 + l1;
}

/* ------------------------------------------------------------------ */
extern "C" void kernel_launch(void* const* d_in, const int* in_sizes, int n_in,
                              void* d_out, int out_size)
{
    const float* x  = (const float*)d_in[0];
    const float* w2 = (const float*)d_in[1];
    const float* b2 = (const float*)d_in[2];
    const float* wa = (const float*)d_in[3];
    const float* ba = (const float*)d_in[4];
    const float* wb = (const float*)d_in[5];
    const float* bb = (const float*)d_in[6];
    const float* Wp = (const float*)d_in[7];
    float* out = (float*)d_out;

    k1_f<<<(BB_*HWPIX)/256, 256>>>(x, w2, b2);

    const int smem_bytes = (CH*HALO_N + 9*CH*CH + CH*CH + 3*CH) * (int)sizeof(float);
    cudaFuncSetAttribute(k2_main, cudaFuncAttributeMaxDynamicSharedMemorySize, smem_bytes);
    dim3 grid(WW/TILE_W, HH/TILE_H, NKP*BB_);
    k2_main<<<grid, 256, smem_bytes>>>(wa, ba, wb, bb, Wp, out);
}

// round 6
// speedup vs baseline: 1.2609x; 1.1350x over previous
#include <cuda_runtime.h>
#include <cuda_bf16.h>
#include <cstdint>
#include <cstddef>

#define NKP 21
#define CH 32
#define BB_ 8
#define HH 96
#define WW 96
#define HWPIX (HH*WW)          /* 9216 */

#define TILE_W 32
#define TILE_H 16
#define HALO_W (TILE_W+2)      /* 34 */
#define HALO_H (TILE_H+2)      /* 18 */
#define HALO_N (HALO_W*HALO_H) /* 612 */

/* scratch: f in [b][c][y][x] layout + per-pixel channel-sum of f */
__device__ float g_f[BB_*CH*HWPIX];
__device__ float g_fsum[BB_*HWPIX];

/* ---- packed f32x2 helpers (sm_100+) ---- */
__device__ __forceinline__ uint64_t pack2(float v) {
    uint64_t r; asm("mov.b64 %0, {%1, %1};" : "=l"(r) : "f"(v)); return r;
}
/* bf16 (top-half-of-f32) -> replicated f32x2, integer path: shift + mov */
__device__ __forceinline__ uint64_t pack2_bf(uint32_t h16) {
    uint32_t f = h16 << 16;
    uint64_t r; asm("mov.b64 %0, {%1, %1};" : "=l"(r) : "r"(f)); return r;
}
__device__ __forceinline__ void ffma2(uint64_t& d, uint64_t a, uint64_t b) {
    asm("fma.rn.f32x2 %0, %1, %2, %0;" : "+l"(d) : "l"(a), "l"(b));
}
__device__ __forceinline__ float2 unpack2(uint64_t v) {
    float2 f; asm("mov.b64 {%0, %1}, %2;" : "=f"(f.x), "=f"(f.y) : "l"(v)); return f;
}

/* ------------------------------------------------------------------ */
/* Kernel 1: f = relu(x @ w2 + b2), stored CHW; fsum = f.sum(ch)       */
/* ------------------------------------------------------------------ */
__global__ void __launch_bounds__(256)
k1_f(const float* __restrict__ x, const float* __restrict__ w2,
     const float* __restrict__ b2)
{
    __shared__ float w2s[CH*CH];
    __shared__ float b2s[CH];
    int tid = threadIdx.x;
    for (int i = tid; i < CH*CH; i += 256) w2s[i] = w2[i];
    if (tid < CH) b2s[tid] = b2[tid];
    __syncthreads();

    int p = blockIdx.x * 256 + tid;          /* pixel in [0, B*HW) — exact grid */

    uint64_t acc[CH/2];
    const uint64_t* b2p = (const uint64_t*)b2s;
#pragma unroll
    for (int j = 0; j < CH/2; j++) acc[j] = b2p[j];

    const float4* xp = (const float4*)(x + (size_t)p * CH);
    const ulonglong2* w2v = (const ulonglong2*)w2s;   /* row = 8 ulonglong2 */
#pragma unroll 2
    for (int c4 = 0; c4 < CH/4; c4++) {
        float4 v = xp[c4];
        float vv[4] = {v.x, v.y, v.z, v.w};
#pragma unroll
        for (int k = 0; k < 4; k++) {
            int c = c4*4 + k;
            uint64_t hv = pack2(vv[k]);
#pragma unroll
            for (int j = 0; j < 8; j++) {
                ulonglong2 w = w2v[c*8 + j];          /* ch 4j..4j+3 */
                ffma2(acc[2*j+0], hv, w.x);
                ffma2(acc[2*j+1], hv, w.y);
            }
        }
    }

    int b   = p / HWPIX;
    int pix = p % HWPIX;
    float s = 0.f;
#pragma unroll
    for (int j = 0; j < CH/2; j++) {
        float2 a = unpack2(acc[j]);
        float f0 = fmaxf(a.x, 0.f);
        float f1 = fmaxf(a.y, 0.f);
        g_f[(size_t)(b*CH + 2*j+0) * HWPIX + pix] = f0;
        g_f[(size_t)(b*CH + 2*j+1) * HWPIX + pix] = f1;
        s += f0 + f1;
    }
    g_fsum[p] = s;
}

/* ------------------------------------------------------------------ */
/* Kernel 2: per (keypoint n, batch b, 32x16 tile)                     */
/*   stage A: h = relu(f @ wa[n] + ba[n]) -> smem bf16 [c][y][x]       */
/*   stage B: g = relu(conv3x3(h, wb[n]) + bb[n]);                     */
/*            out = fsum + sum_d g_d * wpsum[n,d]                      */
/*   2 output pixels per thread; 2 CTAs/SM (smem ~80.5 KB, regs<=128)  */
/* ------------------------------------------------------------------ */
__global__ void __launch_bounds__(256, 2)
k2_main(const float* __restrict__ wa, const float* __restrict__ ba,
        const float* __restrict__ wb, const float* __restrict__ bb,
        const float* __restrict__ Wp, float* __restrict__ out)
{
    extern __shared__ unsigned char smraw[];
    uint16_t* h_s  = (uint16_t*)smraw;                       /* [CH][HALO_N] bf16  39168 B */
    float*    wb_s = (float*)(smraw + CH*HALO_N*2);          /* [9][CH][CH]        36864 B */
    float*    wa_s = wb_s + 9*CH*CH;                         /* [CH][CH]            4096 B */
    float*    wp_s = wa_s + CH*CH;                           /* [CH] */
    float*    ba_s = wp_s + CH;
    float*    bb_s = ba_s + CH;

    int tid = threadIdx.x;
    int n = blockIdx.z / BB_;
    int b = blockIdx.z % BB_;
    int tx0 = blockIdx.x * TILE_W;
    int ty0 = blockIdx.y * TILE_H;

    /* stage weights into smem */
    for (int i = tid; i < 9*CH*CH; i += 256)
        wb_s[i] = wb[(size_t)n*9*CH*CH + i];
    for (int i = tid; i < CH*CH; i += 256)
        wa_s[i] = wa[n*CH*CH + i];
    if (tid < CH) {
        float s = 0.f;
        const float* wpp = Wp + (n*CH + tid)*CH;
#pragma unroll
        for (int o = 0; o < CH; o++) s += wpp[o];
        wp_s[tid] = s;                       /* Wp.sum(-1) */
        ba_s[tid] = ba[n*CH + tid];
        bb_s[tid] = bb[n*CH + tid];
    }
    __syncthreads();

    /* ---- stage A: h over halo (zero outside image = SAME padding) ---- */
    const ulonglong2* wav = (const ulonglong2*)wa_s;
    for (int hp = tid; hp < HALO_N; hp += 256) {
        int hy = hp / HALO_W, hx = hp % HALO_W;
        int gy = ty0 + hy - 1, gx = tx0 + hx - 1;
        bool ok = (gy >= 0) && (gy < HH) && (gx >= 0) && (gx < WW);
        if (ok) {
            const float* fp = g_f + (size_t)b*CH*HWPIX + gy*WW + gx;
            float fv[CH];
#pragma unroll
            for (int e = 0; e < CH; e++) fv[e] = fp[(size_t)e * HWPIX];

            uint64_t acc[CH/2];
            const uint64_t* bap = (const uint64_t*)ba_s;
#pragma unroll
            for (int j = 0; j < CH/2; j++) acc[j] = bap[j];

#pragma unroll 2
            for (int e = 0; e < CH; e++) {
                uint64_t hv = pack2(fv[e]);
#pragma unroll
                for (int j = 0; j < 8; j++) {
                    ulonglong2 w = wav[e*8 + j];
                    ffma2(acc[2*j+0], hv, w.x);
                    ffma2(acc[2*j+1], hv, w.y);
                }
            }
#pragma unroll
            for (int j = 0; j < CH/2; j++) {
                float2 a = unpack2(acc[j]);
                __nv_bfloat16 v0 = __float2bfloat16(fmaxf(a.x, 0.f));
                __nv_bfloat16 v1 = __float2bfloat16(fmaxf(a.y, 0.f));
                h_s[(2*j+0)*HALO_N + hp] = *(uint16_t*)&v0;
                h_s[(2*j+1)*HALO_N + hp] = *(uint16_t*)&v1;
            }
        } else {
#pragma unroll
            for (int d = 0; d < CH; d++) h_s[d*HALO_N + hp] = 0;
        }
    }
    __syncthreads();

    /* ---- stage B: 3x3 conv, 2 output pixels per thread ---- */
    int x  = tid & 31;
    int y0 = tid >> 5;                       /* 0..7 */

    uint64_t acc0[CH/2], acc1[CH/2];
#pragma unroll
    for (int j = 0; j < CH/2; j++) { acc0[j] = 0ull; acc1[j] = 0ull; }

#pragma unroll 1
    for (int t = 0; t < 9; t++) {
        int ky = t / 3, kx = t - 3*ky;
        const uint16_t* hr = h_s + (y0 + ky) * HALO_W + (x + kx);
        const ulonglong2* wr = (const ulonglong2*)(wb_s + t * CH * CH);
#pragma unroll 2
        for (int c = 0; c < CH; c++) {
            const uint16_t* hc = hr + c * HALO_N;
            uint64_t hp0 = pack2_bf((uint32_t)hc[0]);
            uint64_t hp1 = pack2_bf((uint32_t)hc[8*HALO_W]);
#pragma unroll
            for (int j = 0; j < 8; j++) {
                ulonglong2 w = wr[c*8 + j];
                ffma2(acc0[2*j+0], hp0, w.x);
                ffma2(acc0[2*j+1], hp0, w.y);
                ffma2(acc1[2*j+0], hp1, w.x);
                ffma2(acc1[2*j+1], hp1, w.y);
            }
        }
    }

    int gx = tx0 + x;
    float l0 = 0.f, l1 = 0.f;
#pragma unroll
    for (int j = 0; j < CH/2; j++) {
        float2 a0 = unpack2(acc0[j]);
        float2 a1 = unpack2(acc1[j]);
        l0 += fmaxf(a0.x + bb_s[2*j+0], 0.f) * wp_s[2*j+0];
        l0 += fmaxf(a0.y + bb_s[2*j+1], 0.f) * wp_s[2*j+1];
        l1 += fmaxf(a1.x + bb_s[2*j+0], 0.f) * wp_s[2*j+0];
        l1 += fmaxf(a1.y + bb_s[2*j+1], 0.f) * wp_s[2*j+1];
    }

    int gy0 = ty0 + y0;
    int gy1 = gy0 + 8;
    float fs0 = g_fsum[b*HWPIX + gy0*WW + gx];
    float fs1 = g_fsum[b*HWPIX + gy1*WW + gx];
    out[((size_t)(b*HH + gy0)*WW + gx)*NKP + n] = fs0 + l0;
    out[((size_t)(b*HH + gy1)*WW + gx)*NKP + n] = fs1 + l1;
}

/* ------------------------------------------------------------------ */
extern "C" void kernel_launch(void* const* d_in, const int* in_sizes, int n_in,
                              void* d_out, int out_size)
{
    const float* x  = (const float*)d_in[0];
    const float* w2 = (const float*)d_in[1];
    const float* b2 = (const float*)d_in[2];
    const float* wa = (const float*)d_in[3];
    const float* ba = (const float*)d_in[4];
    const float* wb = (const float*)d_in[5];
    const float* bb = (const float*)d_in[6];
    const float* Wp = (const float*)d_in[7];
    float* out = (float*)d_out;

    k1_f<<<(BB_*HWPIX)/256, 256>>>(x, w2, b2);

    const int smem_bytes = CH*HALO_N*2 + (9*CH*CH + CH*CH + 3*CH) * (int)sizeof(float);
    cudaFuncSetAttribute(k2_main, cudaFuncAttributeMaxDynamicSharedMemorySize, smem_bytes);
    dim3 grid(WW/TILE_W, HH/TILE_H, NKP*BB_);
    k2_main<<<grid, 256, smem_bytes>>>(wa, ba, wb, bb, Wp, out);
}

// round 8
// speedup vs baseline: 2.9135x; 2.3107x over previous
#include <cuda_runtime.h>
#include <cuda_bf16.h>
#include <cstdint>
#include <cstddef>

#define NKP 21
#define CH 32
#define BB_ 8
#define HH 96
#define WW 96
#define HWPIX (HH*WW)
#define PW 98
#define PPIX (PW*PW)           /* 9604 */

#define SLABH 8                /* image rows per CTA */
#define HROWS (SLABH+2)        /* 10 halo rows */
#define HALON (HROWS*PW)       /* 980 halo pixels */
#define NST_A 62               /* stage A strips: 62*16=992 >= 980 */
#define NST_B 49               /* stage B strips: 8*98/16 */

#define RSTRIDE 80             /* smem row stride (bytes): conflict-free ldmatrix */

/* smem byte offsets */
#define SM_F    0              /* f: 992 rows x 80B = 79360 */
#define SM_H    79360          /* h: 1008 rows x 80B = 80640 (row r at (r+8)) */
#define SM_WA   160000         /* wa BT bf16: 32 rows x 80B = 2560 */
#define SM_WB   162560         /* wb BT bf16: 9 x 2560 = 23040 */
#define SM_BA   185600         /* f32[32] */
#define SM_BB   185728
#define SM_WP   185856
#define SMEM_SZ 185984

__device__ uint16_t g_fpad[(size_t)BB_*PPIX*CH];   /* f bf16, zero borders */
__device__ float    g_fsum[BB_*HWPIX];

/* ---------------- helpers ---------------- */
__device__ __forceinline__ uint32_t smem_u32(const void* p) {
    uint32_t a;
    asm("{ .reg .u64 t; cvta.to.shared.u64 t, %1; cvt.u32.u64 %0, t; }" : "=r"(a) : "l"(p));
    return a;
}
__device__ __forceinline__ uint64_t pack2(float v) {
    uint64_t r; asm("mov.b64 %0, {%1, %1};" : "=l"(r) : "f"(v)); return r;
}
__device__ __forceinline__ void ffma2(uint64_t& d, uint64_t a, uint64_t b) {
    asm("fma.rn.f32x2 %0, %1, %2, %0;" : "+l"(d) : "l"(a), "l"(b));
}
__device__ __forceinline__ float2 unpack2(uint64_t v) {
    float2 f; asm("mov.b64 {%0, %1}, %2;" : "=f"(f.x), "=f"(f.y) : "l"(v)); return f;
}
/* pack (v0 -> low, v1 -> high) into bf16x2 */
__device__ __forceinline__ uint32_t pk_bf16x2(float v0, float v1) {
    uint32_t r; asm("cvt.rn.bf16x2.f32 %0, %1, %2;" : "=r"(r) : "f"(v1), "f"(v0)); return r;
}
__device__ __forceinline__ void ldsm_x4(uint32_t* r, uint32_t addr) {
    asm volatile("ldmatrix.sync.aligned.m8n8.x4.shared.b16 {%0,%1,%2,%3}, [%4];"
                 : "=r"(r[0]), "=r"(r[1]), "=r"(r[2]), "=r"(r[3]) : "r"(addr));
}
__device__ __forceinline__ void ldsm_x2(uint32_t* r, uint32_t addr) {
    asm volatile("ldmatrix.sync.aligned.m8n8.x2.shared.b16 {%0,%1}, [%2];"
                 : "=r"(r[0]), "=r"(r[1]) : "r"(addr));
}
__device__ __forceinline__ void mma16816(float* c, const uint32_t* a, const uint32_t* b) {
    asm volatile("mma.sync.aligned.m16n8k16.row.col.f32.bf16.bf16.f32 "
                 "{%0,%1,%2,%3}, {%4,%5,%6,%7}, {%8,%9}, {%0,%1,%2,%3};"
                 : "+f"(c[0]), "+f"(c[1]), "+f"(c[2]), "+f"(c[3])
                 : "r"(a[0]), "r"(a[1]), "r"(a[2]), "r"(a[3]), "r"(b[0]), "r"(b[1]));
}

/* ------------------------------------------------------------------ */
/* Kernel 1: f = relu(x @ w2 + b2) -> g_fpad (bf16, 98x98, zero borders) */
/* ------------------------------------------------------------------ */
__global__ void __launch_bounds__(256)
k1_f(const float* __restrict__ x, const float* __restrict__ w2,
     const float* __restrict__ b2)
{
    __shared__ float w2s[CH*CH];
    __shared__ float b2s[CH];
    int tid = threadIdx.x;
    for (int i = tid; i < CH*CH; i += 256) w2s[i] = w2[i];
    if (tid < CH) b2s[tid] = b2[tid];
    __syncthreads();

    int p = blockIdx.x * 256 + tid;
    if (p >= BB_*PPIX) return;
    int b  = p / PPIX;
    int r  = p % PPIX;
    int py = r / PW, px = r % PW;

    uint4* fr = (uint4*)(g_fpad + (size_t)p * CH);

    if (py == 0 || py == PW-1 || px == 0 || px == PW-1) {
        uint4 z = make_uint4(0,0,0,0);
        fr[0] = z; fr[1] = z; fr[2] = z; fr[3] = z;
        return;
    }
    int y = py - 1, xx = px - 1;

    uint64_t acc[CH/2];
    const uint64_t* b2p = (const uint64_t*)b2s;
#pragma unroll
    for (int j = 0; j < CH/2; j++) acc[j] = b2p[j];

    const float4* xp = (const float4*)(x + ((size_t)(b*HH + y)*WW + xx)*CH);
    const ulonglong2* w2v = (const ulonglong2*)w2s;
#pragma unroll 2
    for (int c4 = 0; c4 < CH/4; c4++) {
        float4 v = xp[c4];
        float vv[4] = {v.x, v.y, v.z, v.w};
#pragma unroll
        for (int k = 0; k < 4; k++) {
            uint64_t hv = pack2(vv[k]);
            int c = c4*4 + k;
#pragma unroll
            for (int j = 0; j < 8; j++) {
                ulonglong2 w = w2v[c*8 + j];
                ffma2(acc[2*j+0], hv, w.x);
                ffma2(acc[2*j+1], hv, w.y);
            }
        }
    }

    float s = 0.f;
    uint32_t pk[16];
#pragma unroll
    for (int j = 0; j < CH/2; j++) {
        float2 a = unpack2(acc[j]);
        float f0 = fmaxf(a.x, 0.f);
        float f1 = fmaxf(a.y, 0.f);
        s += f0 + f1;
        pk[j] = pk_bf16x2(f0, f1);
    }
    fr[0] = make_uint4(pk[0],  pk[1],  pk[2],  pk[3]);
    fr[1] = make_uint4(pk[4],  pk[5],  pk[6],  pk[7]);
    fr[2] = make_uint4(pk[8],  pk[9],  pk[10], pk[11]);
    fr[3] = make_uint4(pk[12], pk[13], pk[14], pk[15]);
    g_fsum[b*HWPIX + y*WW + xx] = s;
}

/* ------------------------------------------------------------------ */
/* Kernel 2: per (keypoint n, batch b, 8-row slab) — mma.sync path     */
/* ------------------------------------------------------------------ */
__global__ void __launch_bounds__(256, 1)
k2_main(const float* __restrict__ wa, const float* __restrict__ ba,
        const float* __restrict__ wb, const float* __restrict__ bb,
        const float* __restrict__ Wp, float* __restrict__ out)
{
    extern __shared__ unsigned char smc[];
    uint32_t sb = smem_u32(smc);

    int tid  = threadIdx.x;
    int wid  = tid >> 5;
    int lane = tid & 31;
    int qid  = lane & 3;             /* lane%4: column pair selector   */
    int row4 = lane >> 2;            /* fragment row 0..7              */

    int n   = blockIdx.y / BB_;
    int b   = blockIdx.y % BB_;
    int y0p = blockIdx.x * SLABH;    /* padded-grid base row of slab   */

    /* ---- stage smem: f slab (80B stride), weights, biases ---- */
    {
        const uint4* fsrc = (const uint4*)(g_fpad + ((size_t)b*PPIX + (size_t)y0p*PW) * CH);
        for (int i = tid; i < HALON*4; i += 256) {
            int px = i >> 2, pt = i & 3;
            *(uint4*)(smc + SM_F + px*RSTRIDE + pt*16) = fsrc[i];
        }
        uint4 z = make_uint4(0,0,0,0);
        /* zero f pad rows [980,992): 60 uint4 ; zero h rows [0,8): 40 uint4 */
        if (tid < 60)  *(uint4*)(smc + SM_F + HALON*RSTRIDE + tid*16) = z;
        if (tid >= 64 && tid < 104) *(uint4*)(smc + SM_H + (tid-64)*16) = z;
    }
    {
        uint16_t* was = (uint16_t*)(smc + SM_WA);      /* BT[d][c], row 40 u16 */
        for (int i = tid; i < CH*CH; i += 256) {
            int d = i >> 5, c = i & 31;
            __nv_bfloat16 v = __float2bfloat16(wa[n*CH*CH + c*CH + d]);
            was[d*40 + c] = *(uint16_t*)&v;
        }
        uint16_t* wbs = (uint16_t*)(smc + SM_WB);      /* [tap] BT[d][c] */
        for (int i = tid; i < 9*CH*CH; i += 256) {
            int t = i >> 10, r = i & 1023;
            int d = r >> 5, c = r & 31;
            __nv_bfloat16 v = __float2bfloat16(wb[(size_t)n*9*CH*CH + t*CH*CH + c*CH + d]);
            wbs[t*1280 + d*40 + c] = *(uint16_t*)&v;
        }
    }
    if (tid < CH) {
        ((float*)(smc + SM_BA))[tid] = ba[n*CH + tid];
        ((float*)(smc + SM_BB))[tid] = bb[n*CH + tid];
        float s = 0.f;
        const float* wpp = Wp + (n*CH + tid)*CH;
#pragma unroll
        for (int o = 0; o < CH; o++) s += wpp[o];
        ((float*)(smc + SM_WP))[tid] = s;
    }
    __syncthreads();

    /* ldmatrix lane-address components */
    uint32_t aoffA = (uint32_t)(lane & 15) * RSTRIDE + (uint32_t)(lane >> 4) * 16;
    uint32_t aoffB = (uint32_t)(lane & 7) * RSTRIDE + (uint32_t)((lane >> 3) & 1) * 16;

    /* ---- stage A: h = relu(f @ wa + ba), strips of 16 pixels ---- */
    {
        uint32_t bwa[16];            /* [nb][kh] x2 regs */
#pragma unroll
        for (int nb = 0; nb < 4; nb++) {
#pragma unroll
            for (int kh = 0; kh < 2; kh++)
                ldsm_x2(bwa + (nb*2+kh)*2, sb + SM_WA + nb*8*RSTRIDE + kh*32 + aoffB);
        }
        float ba_r[8];
        const float* ba_s = (const float*)(smc + SM_BA);
#pragma unroll
        for (int nb = 0; nb < 4; nb++) {
            ba_r[nb*2+0] = ba_s[nb*8 + qid*2 + 0];
            ba_r[nb*2+1] = ba_s[nb*8 + qid*2 + 1];
        }

        for (int st = wid; st < NST_A; st += 8) {
            int P = st * 16;
            uint32_t A0[4], A1[4];
            ldsm_x4(A0, sb + SM_F + (uint32_t)P*RSTRIDE + aoffA);
            ldsm_x4(A1, sb + SM_F + (uint32_t)P*RSTRIDE + 32 + aoffA);

            float acc[16];
#pragma unroll
            for (int i = 0; i < 16; i++) acc[i] = 0.f;
#pragma unroll
            for (int nb = 0; nb < 4; nb++) {
                mma16816(acc + nb*4, A0, bwa + (nb*2+0)*2);
                mma16816(acc + nb*4, A1, bwa + (nb*2+1)*2);
            }

            /* epilogue: mask to SAME-pad zeros, +ba, relu, pack, store */
            int p0 = P + row4, p1 = p0 + 8;
            int px0 = p0 % PW, py0 = y0p + p0 / PW;
            int px1 = p1 % PW, py1 = y0p + p1 / PW;
            bool v0 = (p0 < HALON) && (px0 >= 1) && (px0 <= WW) && (py0 >= 1) && (py0 <= HH);
            bool v1 = (p1 < HALON) && (px1 >= 1) && (px1 <= WW) && (py1 >= 1) && (py1 <= HH);
#pragma unroll
            for (int nb = 0; nb < 4; nb++) {
                float e0 = v0 ? fmaxf(acc[nb*4+0] + ba_r[nb*2+0], 0.f) : 0.f;
                float e1 = v0 ? fmaxf(acc[nb*4+1] + ba_r[nb*2+1], 0.f) : 0.f;
                float e2 = v1 ? fmaxf(acc[nb*4+2] + ba_r[nb*2+0], 0.f) : 0.f;
                float e3 = v1 ? fmaxf(acc[nb*4+3] + ba_r[nb*2+1], 0.f) : 0.f;
                *(uint32_t*)(smc + SM_H + (p0+8)*RSTRIDE + nb*16 + qid*4) = pk_bf16x2(e0, e1);
                *(uint32_t*)(smc + SM_H + (p1+8)*RSTRIDE + nb*16 + qid*4) = pk_bf16x2(e2, e3);
            }
        }
    }
    __syncthreads();

    /* ---- stage B: conv3x3 via 9 shifted MMAs + epilogue ---- */
    {
        float bb_r[8], wp_r[8];
        const float* bb_s = (const float*)(smc + SM_BB);
        const float* wp_s = (const float*)(smc + SM_WP);
#pragma unroll
        for (int nb = 0; nb < 4; nb++) {
            bb_r[nb*2+0] = bb_s[nb*8 + qid*2 + 0];
            bb_r[nb*2+1] = bb_s[nb*8 + qid*2 + 1];
            wp_r[nb*2+0] = wp_s[nb*8 + qid*2 + 0];
            wp_r[nb*2+1] = wp_s[nb*8 + qid*2 + 1];
        }

        for (int st = wid; st < NST_B; st += 8) {
            int P = PW + st * 16;    /* output pixels start at halo row 1 */
            float acc[16];
#pragma unroll
            for (int i = 0; i < 16; i++) acc[i] = 0.f;

#pragma unroll 1
            for (int tap = 0; tap < 9; tap++) {
                int s = (tap/3 - 1)*PW + (tap%3 - 1);
                uint32_t abase = sb + SM_H + (uint32_t)(P + s + 8)*RSTRIDE;
                uint32_t A0[4], A1[4];
                ldsm_x4(A0, abase + aoffA);
                ldsm_x4(A1, abase + 32 + aoffA);
                uint32_t wbase = sb + SM_WB + tap*2560;
#pragma unroll
                for (int nb = 0; nb < 4; nb++) {
                    uint32_t b0[2], b1[2];
                    ldsm_x2(b0, wbase + nb*8*RSTRIDE + aoffB);
                    ldsm_x2(b1, wbase + nb*8*RSTRIDE + 32 + aoffB);
                    mma16816(acc + nb*4, A0, b0);
                    mma16816(acc + nb*4, A1, b1);
                }
            }

            /* epilogue: l = sum_ch relu(acc+bb)*wp ; quad reduce; store */
            float l0 = 0.f, l1 = 0.f;
#pragma unroll
            for (int nb = 0; nb < 4; nb++) {
                l0 += fmaxf(acc[nb*4+0] + bb_r[nb*2+0], 0.f) * wp_r[nb*2+0];
                l0 += fmaxf(acc[nb*4+1] + bb_r[nb*2+1], 0.f) * wp_r[nb*2+1];
                l1 += fmaxf(acc[nb*4+2] + bb_r[nb*2+0], 0.f) * wp_r[nb*2+0];
                l1 += fmaxf(acc[nb*4+3] + bb_r[nb*2+1], 0.f) * wp_r[nb*2+1];
            }
            l0 += __shfl_xor_sync(0xffffffffu, l0, 1);
            l0 += __shfl_xor_sync(0xffffffffu, l0, 2);
            l1 += __shfl_xor_sync(0xffffffffu, l1, 1);
            l1 += __shfl_xor_sync(0xffffffffu, l1, 2);

            if (qid == 0) {
                int p0 = P + row4;
                int hx0 = p0 % PW, hy0 = p0 / PW;
                if (hx0 >= 1 && hx0 <= WW) {
                    int idx = (b*HH + (y0p + hy0 - 1))*WW + (hx0 - 1);
                    out[(size_t)idx*NKP + n] = g_fsum[idx] + l0;
                }
                int p1 = p0 + 8;
                int hx1 = p1 % PW, hy1 = p1 / PW;
                if (hx1 >= 1 && hx1 <= WW) {
                    int idx = (b*HH + (y0p + hy1 - 1))*WW + (hx1 - 1);
                    out[(size_t)idx*NKP + n] = g_fsum[idx] + l1;
                }
            }
        }
    }
}

/* ------------------------------------------------------------------ */
extern "C" void kernel_launch(void* const* d_in, const int* in_sizes, int n_in,
                              void* d_out, int out_size)
{
    const float* x  = (const float*)d_in[0];
    const float* w2 = (const float*)d_in[1];
    const float* b2 = (const float*)d_in[2];
    const float* wa = (const float*)d_in[3];
    const float* ba = (const float*)d_in[4];
    const float* wb = (const float*)d_in[5];
    const float* bb = (const float*)d_in[6];
    const float* Wp = (const float*)d_in[7];
    float* out = (float*)d_out;

    k1_f<<<(BB_*PPIX + 255)/256, 256>>>(x, w2, b2);

    cudaFuncSetAttribute(k2_main, cudaFuncAttributeMaxDynamicSharedMemorySize, SMEM_SZ);
    dim3 grid(HH/SLABH, NKP*BB_);
    k2_main<<<grid, 256, SMEM_SZ>>>(wa, ba, wb, bb, Wp, out);
}

// round 9
// speedup vs baseline: 3.8320x; 1.3153x over previous
#include <cuda_runtime.h>
#include <cuda_bf16.h>
#include <cstdint>
#include <cstddef>

#define NKP 21
#define CH 32
#define BB_ 8
#define HH 96
#define WW 96
#define HWPIX (HH*WW)
#define PW 98
#define PPIX (PW*PW)           /* 9604 */

#define SLABH 8                /* image rows per CTA */
#define HROWS (SLABH+2)        /* 10 halo rows */
#define HALON (HROWS*PW)       /* 980 halo pixels */
#define NST_A 62               /* stage A strips: 62*16=992 rows of overlay */
#define NST_B 49               /* stage B strips: 8*98/16 */

#define RSTRIDE 80             /* smem row stride (bytes): conflict-free ldmatrix */

/* smem layout: f/h overlay rows -1..991 -> offset (r+1)*RSTRIDE */
#define SM_FH   0              /* 993 rows x 80B = 79440 */
#define SM_WA   79440          /* wa BT bf16: 32 rows x 80B = 2560 */
#define SM_WB   82000          /* wb BT bf16: 9 x 2560 = 23040 */
#define SM_BA   105040         /* f32[32] */
#define SM_BB   105168
#define SM_WP   105296
#define SMEM_SZ 105424

__device__ uint16_t g_fpad[(size_t)BB_*PPIX*CH];   /* f bf16, zero borders */
__device__ float    g_fsum[BB_*HWPIX];

/* ---------------- helpers ---------------- */
__device__ __forceinline__ uint32_t smem_u32(const void* p) {
    uint32_t a;
    asm("{ .reg .u64 t; cvta.to.shared.u64 t, %1; cvt.u32.u64 %0, t; }" : "=r"(a) : "l"(p));
    return a;
}
__device__ __forceinline__ uint64_t pack2(float v) {
    uint64_t r; asm("mov.b64 %0, {%1, %1};" : "=l"(r) : "f"(v)); return r;
}
__device__ __forceinline__ void ffma2(uint64_t& d, uint64_t a, uint64_t b) {
    asm("fma.rn.f32x2 %0, %1, %2, %0;" : "+l"(d) : "l"(a), "l"(b));
}
__device__ __forceinline__ float2 unpack2(uint64_t v) {
    float2 f; asm("mov.b64 {%0, %1}, %2;" : "=f"(f.x), "=f"(f.y) : "l"(v)); return f;
}
__device__ __forceinline__ uint32_t pk_bf16x2(float v0, float v1) {
    uint32_t r; asm("cvt.rn.bf16x2.f32 %0, %1, %2;" : "=r"(r) : "f"(v1), "f"(v0)); return r;
}
__device__ __forceinline__ void ldsm_x4(uint32_t* r, uint32_t addr) {
    asm volatile("ldmatrix.sync.aligned.m8n8.x4.shared.b16 {%0,%1,%2,%3}, [%4];"
                 : "=r"(r[0]), "=r"(r[1]), "=r"(r[2]), "=r"(r[3]) : "r"(addr));
}
__device__ __forceinline__ void ldsm_x2(uint32_t* r, uint32_t addr) {
    asm volatile("ldmatrix.sync.aligned.m8n8.x2.shared.b16 {%0,%1}, [%2];"
                 : "=r"(r[0]), "=r"(r[1]) : "r"(addr));
}
__device__ __forceinline__ void mma16816(float* c, const uint32_t* a, const uint32_t* b) {
    asm volatile("mma.sync.aligned.m16n8k16.row.col.f32.bf16.bf16.f32 "
                 "{%0,%1,%2,%3}, {%4,%5,%6,%7}, {%8,%9}, {%0,%1,%2,%3};"
                 : "+f"(c[0]), "+f"(c[1]), "+f"(c[2]), "+f"(c[3])
                 : "r"(a[0]), "r"(a[1]), "r"(a[2]), "r"(a[3]), "r"(b[0]), "r"(b[1]));
}

/* ------------------------------------------------------------------ */
/* Kernel 1: f = relu(x @ w2 + b2) -> g_fpad (bf16, 98x98, zero borders) */
/* ------------------------------------------------------------------ */
__global__ void __launch_bounds__(256)
k1_f(const float* __restrict__ x, const float* __restrict__ w2,
     const float* __restrict__ b2)
{
    __shared__ float w2s[CH*CH];
    __shared__ float b2s[CH];
    int tid = threadIdx.x;
    for (int i = tid; i < CH*CH; i += 256) w2s[i] = w2[i];
    if (tid < CH) b2s[tid] = b2[tid];
    __syncthreads();

    int p = blockIdx.x * 256 + tid;
    if (p >= BB_*PPIX) return;
    int b  = p / PPIX;
    int r  = p % PPIX;
    int py = r / PW, px = r % PW;

    uint4* fr = (uint4*)(g_fpad + (size_t)p * CH);

    if (py == 0 || py == PW-1 || px == 0 || px == PW-1) {
        uint4 z = make_uint4(0,0,0,0);
        fr[0] = z; fr[1] = z; fr[2] = z; fr[3] = z;
        return;
    }
    int y = py - 1, xx = px - 1;

    uint64_t acc[CH/2];
    const uint64_t* b2p = (const uint64_t*)b2s;
#pragma unroll
    for (int j = 0; j < CH/2; j++) acc[j] = b2p[j];

    const float4* xp = (const float4*)(x + ((size_t)(b*HH + y)*WW + xx)*CH);
    const ulonglong2* w2v = (const ulonglong2*)w2s;
#pragma unroll 2
    for (int c4 = 0; c4 < CH/4; c4++) {
        float4 v = xp[c4];
        float vv[4] = {v.x, v.y, v.z, v.w};
#pragma unroll
        for (int k = 0; k < 4; k++) {
            uint64_t hv = pack2(vv[k]);
            int c = c4*4 + k;
#pragma unroll
            for (int j = 0; j < 8; j++) {
                ulonglong2 w = w2v[c*8 + j];
                ffma2(acc[2*j+0], hv, w.x);
                ffma2(acc[2*j+1], hv, w.y);
            }
        }
    }

    float s = 0.f;
    uint32_t pk[16];
#pragma unroll
    for (int j = 0; j < CH/2; j++) {
        float2 a = unpack2(acc[j]);
        float f0 = fmaxf(a.x, 0.f);
        float f1 = fmaxf(a.y, 0.f);
        s += f0 + f1;
        pk[j] = pk_bf16x2(f0, f1);
    }
    fr[0] = make_uint4(pk[0],  pk[1],  pk[2],  pk[3]);
    fr[1] = make_uint4(pk[4],  pk[5],  pk[6],  pk[7]);
    fr[2] = make_uint4(pk[8],  pk[9],  pk[10], pk[11]);
    fr[3] = make_uint4(pk[12], pk[13], pk[14], pk[15]);
    g_fsum[b*HWPIX + y*WW + xx] = s;
}

/* ------------------------------------------------------------------ */
/* Kernel 2: per (keypoint n, batch b, 8-row slab) — mma.sync,         */
/* f/h overlay (in-place 1x1 conv) -> 2 CTAs/SM; strip-paired stage B  */
/* ------------------------------------------------------------------ */
__global__ void __launch_bounds__(256, 2)
k2_main(const float* __restrict__ wa, const float* __restrict__ ba,
        const float* __restrict__ wb, const float* __restrict__ bb,
        const float* __restrict__ Wp, float* __restrict__ out)
{
    extern __shared__ unsigned char smc[];
    uint32_t sb = smem_u32(smc);

    int tid  = threadIdx.x;
    int wid  = tid >> 5;
    int lane = tid & 31;
    int qid  = lane & 3;
    int row4 = lane >> 2;

    int n   = blockIdx.y / BB_;
    int b   = blockIdx.y % BB_;
    int y0p = blockIdx.x * SLABH;

    /* ---- stage smem: f slab into overlay (row r at (r+1)*RS), weights ---- */
    {
        const uint4* fsrc = (const uint4*)(g_fpad + ((size_t)b*PPIX + (size_t)y0p*PW) * CH);
        for (int i = tid; i < HALON*4; i += 256) {
            int px = i >> 2, pt = i & 3;
            *(uint4*)(smc + SM_FH + (px+1)*RSTRIDE + pt*16) = fsrc[i];
        }
        /* zero pad rows: slot 0 (row -1) and slots 981..992 (rows 980..991) */
        if (tid < 65) {
            int s5 = tid / 5, pt = tid % 5;
            int slot = (s5 == 0) ? 0 : (980 + s5);
            *(uint4*)(smc + SM_FH + slot*RSTRIDE + pt*16) = make_uint4(0,0,0,0);
        }
    }
    {
        uint16_t* was = (uint16_t*)(smc + SM_WA);      /* BT[d][c], row 40 u16 */
        for (int i = tid; i < CH*CH; i += 256) {
            int d = i >> 5, c = i & 31;
            __nv_bfloat16 v = __float2bfloat16(wa[n*CH*CH + c*CH + d]);
            was[d*40 + c] = *(uint16_t*)&v;
        }
        uint16_t* wbs = (uint16_t*)(smc + SM_WB);      /* [tap] BT[d][c] */
        for (int i = tid; i < 9*CH*CH; i += 256) {
            int t = i >> 10, r = i & 1023;
            int d = r >> 5, c = r & 31;
            __nv_bfloat16 v = __float2bfloat16(wb[(size_t)n*9*CH*CH + t*CH*CH + c*CH + d]);
            wbs[t*1280 + d*40 + c] = *(uint16_t*)&v;
        }
    }
    if (tid < CH) {
        ((float*)(smc + SM_BA))[tid] = ba[n*CH + tid];
        ((float*)(smc + SM_BB))[tid] = bb[n*CH + tid];
        float s = 0.f;
        const float* wpp = Wp + (n*CH + tid)*CH;
#pragma unroll
        for (int o = 0; o < CH; o++) s += wpp[o];
        ((float*)(smc + SM_WP))[tid] = s;
    }
    __syncthreads();

    uint32_t aoffA = (uint32_t)(lane & 15) * RSTRIDE + (uint32_t)(lane >> 4) * 16;
    uint32_t aoffB = (uint32_t)(lane & 7) * RSTRIDE + (uint32_t)((lane >> 3) & 1) * 16;

    /* ---- stage A: h = relu(f @ wa + ba), in-place over f ---- */
    {
        uint32_t bwa[16];
#pragma unroll
        for (int nb = 0; nb < 4; nb++) {
#pragma unroll
            for (int kh = 0; kh < 2; kh++)
                ldsm_x2(bwa + (nb*2+kh)*2, sb + SM_WA + nb*8*RSTRIDE + kh*32 + aoffB);
        }
        float ba_r[8];
        const float* ba_s = (const float*)(smc + SM_BA);
#pragma unroll
        for (int nb = 0; nb < 4; nb++) {
            ba_r[nb*2+0] = ba_s[nb*8 + qid*2 + 0];
            ba_r[nb*2+1] = ba_s[nb*8 + qid*2 + 1];
        }

        for (int st = wid; st < NST_A; st += 8) {
            int P = st * 16;
            uint32_t abase = sb + SM_FH + (uint32_t)(P+1)*RSTRIDE;
            uint32_t A0[4], A1[4];
            ldsm_x4(A0, abase + aoffA);
            ldsm_x4(A1, abase + 32 + aoffA);

            float acc[16];
#pragma unroll
            for (int i = 0; i < 16; i++) acc[i] = 0.f;
#pragma unroll
            for (int nb = 0; nb < 4; nb++) {
                mma16816(acc + nb*4, A0, bwa + (nb*2+0)*2);
                mma16816(acc + nb*4, A1, bwa + (nb*2+1)*2);
            }

            int p0 = P + row4, p1 = p0 + 8;
            int px0 = p0 % PW, py0 = y0p + p0 / PW;
            int px1 = p1 % PW, py1 = y0p + p1 / PW;
            bool v0 = (p0 < HALON) && (px0 >= 1) && (px0 <= WW) && (py0 >= 1) && (py0 <= HH);
            bool v1 = (p1 < HALON) && (px1 >= 1) && (px1 <= WW) && (py1 >= 1) && (py1 <= HH);
#pragma unroll
            for (int nb = 0; nb < 4; nb++) {
                float e0 = v0 ? fmaxf(acc[nb*4+0] + ba_r[nb*2+0], 0.f) : 0.f;
                float e1 = v0 ? fmaxf(acc[nb*4+1] + ba_r[nb*2+1], 0.f) : 0.f;
                float e2 = v1 ? fmaxf(acc[nb*4+2] + ba_r[nb*2+0], 0.f) : 0.f;
                float e3 = v1 ? fmaxf(acc[nb*4+3] + ba_r[nb*2+1], 0.f) : 0.f;
                *(uint32_t*)(smc + SM_FH + (p0+1)*RSTRIDE + nb*16 + qid*4) = pk_bf16x2(e0, e1);
                *(uint32_t*)(smc + SM_FH + (p1+1)*RSTRIDE + nb*16 + qid*4) = pk_bf16x2(e2, e3);
            }
        }
    }
    __syncthreads();

    /* ---- stage B: conv3x3 via 9 shifted MMAs, strip pairs (st, st+8) ---- */
    {
        float bb_r[8], wp_r[8];
        const float* bb_s = (const float*)(smc + SM_BB);
        const float* wp_s = (const float*)(smc + SM_WP);
#pragma unroll
        for (int nb = 0; nb < 4; nb++) {
            bb_r[nb*2+0] = bb_s[nb*8 + qid*2 + 0];
            bb_r[nb*2+1] = bb_s[nb*8 + qid*2 + 1];
            wp_r[nb*2+0] = wp_s[nb*8 + qid*2 + 0];
            wp_r[nb*2+1] = wp_s[nb*8 + qid*2 + 1];
        }

        for (int base = wid; base < NST_B; base += 16) {
            int st2 = base + 8;
            bool two = (st2 < NST_B);
            int P1 = PW + base * 16;
            int P2 = PW + st2  * 16;

            float acc1[16], acc2[16];
#pragma unroll
            for (int i = 0; i < 16; i++) { acc1[i] = 0.f; acc2[i] = 0.f; }

#pragma unroll 1
            for (int tap = 0; tap < 9; tap++) {
                int s = (tap/3 - 1)*PW + (tap%3 - 1);
                uint32_t a1 = sb + SM_FH + (uint32_t)(P1 + s + 1)*RSTRIDE;
                uint32_t A10[4], A11[4], A20[4], A21[4];
                ldsm_x4(A10, a1 + aoffA);
                ldsm_x4(A11, a1 + 32 + aoffA);
                if (two) {
                    uint32_t a2 = sb + SM_FH + (uint32_t)(P2 + s + 1)*RSTRIDE;
                    ldsm_x4(A20, a2 + aoffA);
                    ldsm_x4(A21, a2 + 32 + aoffA);
                }
                uint32_t wbase = sb + SM_WB + tap*2560;
#pragma unroll
                for (int nb = 0; nb < 4; nb++) {
                    uint32_t b0[2], b1[2];
                    ldsm_x2(b0, wbase + nb*8*RSTRIDE + aoffB);
                    ldsm_x2(b1, wbase + nb*8*RSTRIDE + 32 + aoffB);
                    mma16816(acc1 + nb*4, A10, b0);
                    mma16816(acc1 + nb*4, A11, b1);
                    if (two) {
                        mma16816(acc2 + nb*4, A20, b0);
                        mma16816(acc2 + nb*4, A21, b1);
                    }
                }
            }

#pragma unroll
            for (int which = 0; which < 2; which++) {
                if (which == 1 && !two) break;
                float* acc = which ? acc2 : acc1;
                int P = which ? P2 : P1;
                float l0 = 0.f, l1 = 0.f;
#pragma unroll
                for (int nb = 0; nb < 4; nb++) {
                    l0 += fmaxf(acc[nb*4+0] + bb_r[nb*2+0], 0.f) * wp_r[nb*2+0];
                    l0 += fmaxf(acc[nb*4+1] + bb_r[nb*2+1], 0.f) * wp_r[nb*2+1];
                    l1 += fmaxf(acc[nb*4+2] + bb_r[nb*2+0], 0.f) * wp_r[nb*2+0];
                    l1 += fmaxf(acc[nb*4+3] + bb_r[nb*2+1], 0.f) * wp_r[nb*2+1];
                }
                l0 += __shfl_xor_sync(0xffffffffu, l0, 1);
                l0 += __shfl_xor_sync(0xffffffffu, l0, 2);
                l1 += __shfl_xor_sync(0xffffffffu, l1, 1);
                l1 += __shfl_xor_sync(0xffffffffu, l1, 2);

                if (qid == 0) {
                    int p0 = P + row4;
                    int hx0 = p0 % PW, hy0 = p0 / PW;
                    if (hx0 >= 1 && hx0 <= WW) {
                        int idx = (b*HH + (y0p + hy0 - 1))*WW + (hx0 - 1);
                        out[(size_t)idx*NKP + n] = g_fsum[idx] + l0;
                    }
                    int p1 = p0 + 8;
                    int hx1 = p1 % PW, hy1 = p1 / PW;
                    if (hx1 >= 1 && hx1 <= WW) {
                        int idx = (b*HH + (y0p + hy1 - 1))*WW + (hx1 - 1);
                        out[(size_t)idx*NKP + n] = g_fsum[idx] + l1;
                    }
                }
            }
        }
    }
}

/* ------------------------------------------------------------------ */
extern "C" void kernel_launch(void* const* d_in, const int* in_sizes, int n_in,
                              void* d_out, int out_size)
{
    const float* x  = (const float*)d_in[0];
    const float* w2 = (const float*)d_in[1];
    const float* b2 = (const float*)d_in[2];
    const float* wa = (const float*)d_in[3];
    const float* ba = (const float*)d_in[4];
    const float* wb = (const float*)d_in[5];
    const float* bb = (const float*)d_in[6];
    const float* Wp = (const float*)d_in[7];
    float* out = (float*)d_out;

    k1_f<<<(BB_*PPIX + 255)/256, 256>>>(x, w2, b2);

    cudaFuncSetAttribute(k2_main, cudaFuncAttributeMaxDynamicSharedMemorySize, SMEM_SZ);
    dim3 grid(HH/SLABH, NKP*BB_);
    k2_main<<<grid, 256, SMEM_SZ>>>(wa, ba, wb, bb, Wp, out);
}

// round 11
// speedup vs baseline: 4.4202x; 1.1535x over previous
#include <cuda_runtime.h>
#include <cuda_bf16.h>
#include <cstdint>
#include <cstddef>

#define NKP 21
#define CH 32
#define BB_ 8
#define HH 96
#define WW 96
#define HWPIX (HH*WW)
#define PW 98
#define PPIX (PW*PW)           /* 9604 */

#define SLABH 8                /* image rows per CTA */
#define HROWS (SLABH+2)        /* 10 halo rows */
#define HALON (HROWS*PW)       /* 980 halo pixels */
#define NST_A 62               /* stage A strips */
#define NST_B 49               /* stage B strips */

#define RSTRIDE 80             /* smem row stride (bytes) */

/* smem layout: f/h overlay rows -1..991 -> offset (r+1)*RSTRIDE */
#define SM_FH   0              /* 993 rows x 80B = 79440 */
#define SM_WA   79440          /* wa BT bf16: 32 rows x 80B = 2560 */
#define SM_WB   82000          /* wb BT bf16: 9 x 2560 = 23040 */
#define SM_BA   105040         /* f32[32] */
#define SM_BB   105168
#define SM_WP   105296
#define SMEM_SZ 105424

__device__ uint16_t g_fpad[(size_t)BB_*PPIX*CH];
__device__ float    g_fsum[BB_*HWPIX];

/* ---------------- helpers ---------------- */
__device__ __forceinline__ uint32_t smem_u32(const void* p) {
    uint32_t a;
    asm("{ .reg .u64 t; cvta.to.shared.u64 t, %1; cvt.u32.u64 %0, t; }" : "=r"(a) : "l"(p));
    return a;
}
__device__ __forceinline__ uint64_t pack2(float v) {
    uint64_t r; asm("mov.b64 %0, {%1, %1};" : "=l"(r) : "f"(v)); return r;
}
__device__ __forceinline__ void ffma2(uint64_t& d, uint64_t a, uint64_t b) {
    asm("fma.rn.f32x2 %0, %1, %2, %0;" : "+l"(d) : "l"(a), "l"(b));
}
__device__ __forceinline__ float2 unpack2(uint64_t v) {
    float2 f; asm("mov.b64 {%0, %1}, %2;" : "=f"(f.x), "=f"(f.y) : "l"(v)); return f;
}
__device__ __forceinline__ uint32_t pk_bf16x2(float v0, float v1) {
    uint32_t r; asm("cvt.rn.bf16x2.f32 %0, %1, %2;" : "=r"(r) : "f"(v1), "f"(v0)); return r;
}
__device__ __forceinline__ void ldsm_x4(uint32_t* r, uint32_t addr) {
    asm volatile("ldmatrix.sync.aligned.m8n8.x4.shared.b16 {%0,%1,%2,%3}, [%4];"
                 : "=r"(r[0]), "=r"(r[1]), "=r"(r[2]), "=r"(r[3]) : "r"(addr));
}
__device__ __forceinline__ void mma16816(float* c, const uint32_t* a, const uint32_t* b) {
    asm volatile("mma.sync.aligned.m16n8k16.row.col.f32.bf16.bf16.f32 "
                 "{%0,%1,%2,%3}, {%4,%5,%6,%7}, {%8,%9}, {%0,%1,%2,%3};"
                 : "+f"(c[0]), "+f"(c[1]), "+f"(c[2]), "+f"(c[3])
                 : "r"(a[0]), "r"(a[1]), "r"(a[2]), "r"(a[3]), "r"(b[0]), "r"(b[1]));
}

/* ------------------------------------------------------------------ */
/* Kernel 1: f = relu(x @ w2 + b2) -> g_fpad (bf16, 98x98, zero borders) */
/* ------------------------------------------------------------------ */
__global__ void __launch_bounds__(256)
k1_f(const float* __restrict__ x, const float* __restrict__ w2,
     const float* __restrict__ b2)
{
    __shared__ float w2s[CH*CH];
    __shared__ float b2s[CH];
    int tid = threadIdx.x;
    for (int i = tid; i < CH*CH; i += 256) w2s[i] = w2[i];
    if (tid < CH) b2s[tid] = b2[tid];
    __syncthreads();

    int p = blockIdx.x * 256 + tid;
    if (p >= BB_*PPIX) return;
    int b  = p / PPIX;
    int r  = p % PPIX;
    int py = r / PW, px = r % PW;

    uint4* fr = (uint4*)(g_fpad + (size_t)p * CH);

    if (py == 0 || py == PW-1 || px == 0 || px == PW-1) {
        uint4 z = make_uint4(0,0,0,0);
        fr[0] = z; fr[1] = z; fr[2] = z; fr[3] = z;
        return;
    }
    int y = py - 1, xx = px - 1;

    uint64_t acc[CH/2];
    const uint64_t* b2p = (const uint64_t*)b2s;
#pragma unroll
    for (int j = 0; j < CH/2; j++) acc[j] = b2p[j];

    const float4* xp = (const float4*)(x + ((size_t)(b*HH + y)*WW + xx)*CH);
    const ulonglong2* w2v = (const ulonglong2*)w2s;
#pragma unroll 2
    for (int c4 = 0; c4 < CH/4; c4++) {
        float4 v = xp[c4];
        float vv[4] = {v.x, v.y, v.z, v.w};
#pragma unroll
        for (int k = 0; k < 4; k++) {
            uint64_t hv = pack2(vv[k]);
            int c = c4*4 + k;
#pragma unroll
            for (int j = 0; j < 8; j++) {
                ulonglong2 w = w2v[c*8 + j];
                ffma2(acc[2*j+0], hv, w.x);
                ffma2(acc[2*j+1], hv, w.y);
            }
        }
    }

    float s = 0.f;
    uint32_t pk[16];
#pragma unroll
    for (int j = 0; j < CH/2; j++) {
        float2 a = unpack2(acc[j]);
        float f0 = fmaxf(a.x, 0.f);
        float f1 = fmaxf(a.y, 0.f);
        s += f0 + f1;
        pk[j] = pk_bf16x2(f0, f1);
    }
    fr[0] = make_uint4(pk[0],  pk[1],  pk[2],  pk[3]);
    fr[1] = make_uint4(pk[4],  pk[5],  pk[6],  pk[7]);
    fr[2] = make_uint4(pk[8],  pk[9],  pk[10], pk[11]);
    fr[3] = make_uint4(pk[12], pk[13], pk[14], pk[15]);
    g_fsum[b*HWPIX + y*WW + xx] = s;
}

/* ------------------------------------------------------------------ */
/* Kernel 2: per (keypoint n, batch b, 8-row slab) — mma.sync          */
/* tap-outer stage B, 2 passes x 3 strips/warp, B hoisted per tap      */
/* ------------------------------------------------------------------ */
__global__ void __launch_bounds__(256, 2)
k2_main(const float* __restrict__ wa, const float* __restrict__ ba,
        const float* __restrict__ wb, const float* __restrict__ bb,
        const float* __restrict__ Wp, float* __restrict__ out)
{
    extern __shared__ unsigned char smc[];
    uint32_t sb = smem_u32(smc);

    int tid  = threadIdx.x;
    int wid  = tid >> 5;
    int lane = tid & 31;
    int qid  = lane & 3;
    int row4 = lane >> 2;

    int n   = blockIdx.y / BB_;
    int b   = blockIdx.y % BB_;
    int y0p = blockIdx.x * SLABH;

    /* ---- stage smem ---- */
    {
        const uint4* fsrc = (const uint4*)(g_fpad + ((size_t)b*PPIX + (size_t)y0p*PW) * CH);
        for (int i = tid; i < HALON*4; i += 256) {
            int px = i >> 2, pt = i & 3;
            *(uint4*)(smc + SM_FH + (px+1)*RSTRIDE + pt*16) = fsrc[i];
        }
        if (tid < 65) {
            int s5 = tid / 5, pt = tid % 5;
            int slot = (s5 == 0) ? 0 : (980 + s5);
            *(uint4*)(smc + SM_FH + slot*RSTRIDE + pt*16) = make_uint4(0,0,0,0);
        }
    }
    {
        uint16_t* was = (uint16_t*)(smc + SM_WA);
        for (int i = tid; i < CH*CH; i += 256) {
            int d = i >> 5, c = i & 31;
            __nv_bfloat16 v = __float2bfloat16(wa[n*CH*CH + c*CH + d]);
            was[d*40 + c] = *(uint16_t*)&v;
        }
        uint16_t* wbs = (uint16_t*)(smc + SM_WB);
        for (int i = tid; i < 9*CH*CH; i += 256) {
            int t = i >> 10, r = i & 1023;
            int d = r >> 5, c = r & 31;
            __nv_bfloat16 v = __float2bfloat16(wb[(size_t)n*9*CH*CH + t*CH*CH + c*CH + d]);
            wbs[t*1280 + d*40 + c] = *(uint16_t*)&v;
        }
    }
    if (tid < CH) {
        ((float*)(smc + SM_BA))[tid] = ba[n*CH + tid];
        ((float*)(smc + SM_BB))[tid] = bb[n*CH + tid];
        float s = 0.f;
        const float* wpp = Wp + (n*CH + tid)*CH;
#pragma unroll
        for (int o = 0; o < CH; o++) s += wpp[o];
        ((float*)(smc + SM_WP))[tid] = s;
    }
    __syncthreads();

    uint32_t aoffA  = (uint32_t)(lane & 15) * RSTRIDE + (uint32_t)(lane >> 4) * 16;
    uint32_t aoffB4 = (uint32_t)(lane & 7)  * RSTRIDE + (uint32_t)(lane >> 3) * 16;

    /* ---- stage A: h = relu(f @ wa + ba), in-place over f ---- */
    {
        uint32_t bwa[16];
#pragma unroll
        for (int nb = 0; nb < 4; nb++)
            ldsm_x4(bwa + nb*4, sb + SM_WA + nb*8*RSTRIDE + aoffB4);
        float ba_r[8];
        const float* ba_s = (const float*)(smc + SM_BA);
#pragma unroll
        for (int nb = 0; nb < 4; nb++) {
            ba_r[nb*2+0] = ba_s[nb*8 + qid*2 + 0];
            ba_r[nb*2+1] = ba_s[nb*8 + qid*2 + 1];
        }

        for (int st = wid; st < NST_A; st += 8) {
            int P = st * 16;
            uint32_t abase = sb + SM_FH + (uint32_t)(P+1)*RSTRIDE;
            uint32_t A0[4], A1[4];
            ldsm_x4(A0, abase + aoffA);
            ldsm_x4(A1, abase + 32 + aoffA);

            float acc[16];
#pragma unroll
            for (int i = 0; i < 16; i++) acc[i] = 0.f;
#pragma unroll
            for (int nb = 0; nb < 4; nb++) {
                mma16816(acc + nb*4, A0, bwa + nb*4);
                mma16816(acc + nb*4, A1, bwa + nb*4 + 2);
            }

            int p0 = P + row4, p1 = p0 + 8;
            int px0 = p0 % PW, py0 = y0p + p0 / PW;
            int px1 = p1 % PW, py1 = y0p + p1 / PW;
            bool v0 = (p0 < HALON) && (px0 >= 1) && (px0 <= WW) && (py0 >= 1) && (py0 <= HH);
            bool v1 = (p1 < HALON) && (px1 >= 1) && (px1 <= WW) && (py1 >= 1) && (py1 <= HH);
#pragma unroll
            for (int nb = 0; nb < 4; nb++) {
                float e0 = v0 ? fmaxf(acc[nb*4+0] + ba_r[nb*2+0], 0.f) : 0.f;
                float e1 = v0 ? fmaxf(acc[nb*4+1] + ba_r[nb*2+1], 0.f) : 0.f;
                float e2 = v1 ? fmaxf(acc[nb*4+2] + ba_r[nb*2+0], 0.f) : 0.f;
                float e3 = v1 ? fmaxf(acc[nb*4+3] + ba_r[nb*2+1], 0.f) : 0.f;
                *(uint32_t*)(smc + SM_FH + (p0+1)*RSTRIDE + nb*16 + qid*4) = pk_bf16x2(e0, e1);
                *(uint32_t*)(smc + SM_FH + (p1+1)*RSTRIDE + nb*16 + qid*4) = pk_bf16x2(e2, e3);
            }
        }
    }
    __syncthreads();

    /* ---- stage B: 2 passes x (tap-outer, 3 strips/warp, B hoisted) ---- */
    {
        float bb_r[8], wp_r[8];
        const float* bb_s = (const float*)(smc + SM_BB);
        const float* wp_s = (const float*)(smc + SM_WP);
#pragma unroll
        for (int nb = 0; nb < 4; nb++) {
            bb_r[nb*2+0] = bb_s[nb*8 + qid*2 + 0];
            bb_r[nb*2+1] = bb_s[nb*8 + qid*2 + 1];
            wp_r[nb*2+0] = wp_s[nb*8 + qid*2 + 0];
            wp_r[nb*2+1] = wp_s[nb*8 + qid*2 + 1];
        }

#pragma unroll 1
        for (int g = 0; g < 2; g++) {
            /* strips: wid + g*8 + {0,16,32}  -> covers 0..47 over both passes */
            float acc[3][16];
#pragma unroll
            for (int k = 0; k < 3; k++)
#pragma unroll
                for (int i = 0; i < 16; i++) acc[k][i] = 0.f;

#pragma unroll 1
            for (int tap = 0; tap < 9; tap++) {
                int s = (tap/3 - 1)*PW + (tap%3 - 1);
                uint32_t wbase = sb + SM_WB + tap*2560;
                uint32_t bw[16];
#pragma unroll
                for (int nb = 0; nb < 4; nb++)
                    ldsm_x4(bw + nb*4, wbase + nb*8*RSTRIDE + aoffB4);

#pragma unroll
                for (int k = 0; k < 3; k++) {
                    int P = PW + (wid + g*8 + k*16) * 16;
                    uint32_t abase = sb + SM_FH + (uint32_t)(P + s + 1)*RSTRIDE;
                    uint32_t A0[4], A1[4];
                    ldsm_x4(A0, abase + aoffA);
                    ldsm_x4(A1, abase + 32 + aoffA);
#pragma unroll
                    for (int nb = 0; nb < 4; nb++) {
                        mma16816(acc[k] + nb*4, A0, bw + nb*4);
                        mma16816(acc[k] + nb*4, A1, bw + nb*4 + 2);
                    }
                }
            }

#pragma unroll
            for (int k = 0; k < 3; k++) {
                int P = PW + (wid + g*8 + k*16) * 16;
                float l0 = 0.f, l1 = 0.f;
#pragma unroll
                for (int nb = 0; nb < 4; nb++) {
                    l0 += fmaxf(acc[k][nb*4+0] + bb_r[nb*2+0], 0.f) * wp_r[nb*2+0];
                    l0 += fmaxf(acc[k][nb*4+1] + bb_r[nb*2+1], 0.f) * wp_r[nb*2+1];
                    l1 += fmaxf(acc[k][nb*4+2] + bb_r[nb*2+0], 0.f) * wp_r[nb*2+0];
                    l1 += fmaxf(acc[k][nb*4+3] + bb_r[nb*2+1], 0.f) * wp_r[nb*2+1];
                }
                l0 += __shfl_xor_sync(0xffffffffu, l0, 1);
                l0 += __shfl_xor_sync(0xffffffffu, l0, 2);
                l1 += __shfl_xor_sync(0xffffffffu, l1, 1);
                l1 += __shfl_xor_sync(0xffffffffu, l1, 2);

                if (qid == 0) {
                    int p0 = P + row4;
                    int hx0 = p0 % PW, hy0 = p0 / PW;
                    if (hx0 >= 1 && hx0 <= WW) {
                        int idx = (b*HH + (y0p + hy0 - 1))*WW + (hx0 - 1);
                        out[(size_t)idx*NKP + n] = g_fsum[idx] + l0;
                    }
                    int p1 = p0 + 8;
                    int hx1 = p1 % PW, hy1 = p1 / PW;
                    if (hx1 >= 1 && hx1 <= WW) {
                        int idx = (b*HH + (y0p + hy1 - 1))*WW + (hx1 - 1);
                        out[(size_t)idx*NKP + n] = g_fsum[idx] + l1;
                    }
                }
            }
        }

        /* leftover strip 48 (warp 0 only) */
        if (wid == 0) {
            int P = PW + 48 * 16;
            float a4[16];
#pragma unroll
            for (int i = 0; i < 16; i++) a4[i] = 0.f;
#pragma unroll 1
            for (int tap = 0; tap < 9; tap++) {
                int s = (tap/3 - 1)*PW + (tap%3 - 1);
                uint32_t wbase = sb + SM_WB + tap*2560;
                uint32_t abase = sb + SM_FH + (uint32_t)(P + s + 1)*RSTRIDE;
                uint32_t A0[4], A1[4];
                ldsm_x4(A0, abase + aoffA);
                ldsm_x4(A1, abase + 32 + aoffA);
#pragma unroll
                for (int nb = 0; nb < 4; nb++) {
                    uint32_t bw4[4];
                    ldsm_x4(bw4, wbase + nb*8*RSTRIDE + aoffB4);
                    mma16816(a4 + nb*4, A0, bw4);
                    mma16816(a4 + nb*4, A1, bw4 + 2);
                }
            }
            float l0 = 0.f, l1 = 0.f;
#pragma unroll
            for (int nb = 0; nb < 4; nb++) {
                l0 += fmaxf(a4[nb*4+0] + bb_r[nb*2+0], 0.f) * wp_r[nb*2+0];
                l0 += fmaxf(a4[nb*4+1] + bb_r[nb*2+1], 0.f) * wp_r[nb*2+1];
                l1 += fmaxf(a4[nb*4+2] + bb_r[nb*2+0], 0.f) * wp_r[nb*2+0];
                l1 += fmaxf(a4[nb*4+3] + bb_r[nb*2+1], 0.f) * wp_r[nb*2+1];
            }
            l0 += __shfl_xor_sync(0xffffffffu, l0, 1);
            l0 += __shfl_xor_sync(0xffffffffu, l0, 2);
            l1 += __shfl_xor_sync(0xffffffffu, l1, 1);
            l1 += __shfl_xor_sync(0xffffffffu, l1, 2);
            if (qid == 0) {
                int p0 = P + row4;
                int hx0 = p0 % PW, hy0 = p0 / PW;
                if (hx0 >= 1 && hx0 <= WW) {
                    int idx = (b*HH + (y0p + hy0 - 1))*WW + (hx0 - 1);
                    out[(size_t)idx*NKP + n] = g_fsum[idx] + l0;
                }
                int p1 = p0 + 8;
                int hx1 = p1 % PW, hy1 = p1 / PW;
                if (hx1 >= 1 && hx1 <= WW) {
                    int idx = (b*HH + (y0p + hy1 - 1))*WW + (hx1 - 1);
                    out[(size_t)idx*NKP + n] = g_fsum[idx] + l1;
                }
            }
        }
    }
}

/* ------------------------------------------------------------------ */
extern "C" void kernel_launch(void* const* d_in, const int* in_sizes, int n_in,
                              void* d_out, int out_size)
{
    const float* x  = (const float*)d_in[0];
    const float* w2 = (const float*)d_in[1];
    const float* b2 = (const float*)d_in[2];
    const float* wa = (const float*)d_in[3];
    const float* ba = (const float*)d_in[4];
    const float* wb = (const float*)d_in[5];
    const float* bb = (const float*)d_in[6];
    const float* Wp = (const float*)d_in[7];
    float* out = (float*)d_out;

    k1_f<<<(BB_*PPIX + 255)/256, 256>>>(x, w2, b2);

    cudaFuncSetAttribute(k2_main, cudaFuncAttributeMaxDynamicSharedMemorySize, SMEM_SZ);
    dim3 grid(HH/SLABH, NKP*BB_);
    k2_main<<<grid, 256, SMEM_SZ>>>(wa, ba, wb, bb, Wp, out);
}

// round 12
// speedup vs baseline: 4.6521x; 1.0525x over previous
#include <cuda_runtime.h>
#include <cuda_bf16.h>
#include <cstdint>
#include <cstddef>

#define NKP 21
#define CH 32
#define BB_ 8
#define HH 96
#define WW 96
#define HWPIX (HH*WW)
#define PW 98
#define PPIX (PW*PW)           /* 9604 */

#define SLABH 8                /* image rows per CTA */
#define HROWS (SLABH+2)        /* 10 halo rows */
#define HALON (HROWS*PW)       /* 980 halo pixels */
#define NST_A 62               /* stage A strips */
#define NST_B 49               /* stage B strips */

#define RSTRIDE 80             /* smem row stride (bytes) */

/* smem layout: f/h overlay rows -1..991 -> offset (r+1)*RSTRIDE */
#define SM_FH   0              /* 993 rows x 80B = 79440 */
#define SM_WA   79440          /* wa BT bf16: 32 rows x 80B = 2560 */
#define SM_WB   82000          /* wb BT bf16: 9 x 2560 = 23040 */
#define SM_BA   105040         /* f32[32] */
#define SM_BB   105168
#define SM_WP   105296
#define SMEM_SZ 105424

__device__ uint16_t g_fpad[(size_t)BB_*PPIX*CH];
__device__ float    g_fsum[BB_*HWPIX];

/* ---------------- helpers ---------------- */
__device__ __forceinline__ uint32_t smem_u32(const void* p) {
    uint32_t a;
    asm("{ .reg .u64 t; cvta.to.shared.u64 t, %1; cvt.u32.u64 %0, t; }" : "=r"(a) : "l"(p));
    return a;
}
__device__ __forceinline__ uint64_t pack2(float v) {
    uint64_t r; asm("mov.b64 %0, {%1, %1};" : "=l"(r) : "f"(v)); return r;
}
__device__ __forceinline__ void ffma2(uint64_t& d, uint64_t a, uint64_t b) {
    asm("fma.rn.f32x2 %0, %1, %2, %0;" : "+l"(d) : "l"(a), "l"(b));
}
__device__ __forceinline__ float2 unpack2(uint64_t v) {
    float2 f; asm("mov.b64 {%0, %1}, %2;" : "=f"(f.x), "=f"(f.y) : "l"(v)); return f;
}
__device__ __forceinline__ uint32_t pk_bf16x2(float v0, float v1) {
    uint32_t r; asm("cvt.rn.bf16x2.f32 %0, %1, %2;" : "=r"(r) : "f"(v1), "f"(v0)); return r;
}
__device__ __forceinline__ void ldsm_x4(uint32_t* r, uint32_t addr) {
    asm volatile("ldmatrix.sync.aligned.m8n8.x4.shared.b16 {%0,%1,%2,%3}, [%4];"
                 : "=r"(r[0]), "=r"(r[1]), "=r"(r[2]), "=r"(r[3]) : "r"(addr));
}
__device__ __forceinline__ void mma16816(float* c, const uint32_t* a, const uint32_t* b) {
    asm volatile("mma.sync.aligned.m16n8k16.row.col.f32.bf16.bf16.f32 "
                 "{%0,%1,%2,%3}, {%4,%5,%6,%7}, {%8,%9}, {%0,%1,%2,%3};"
                 : "+f"(c[0]), "+f"(c[1]), "+f"(c[2]), "+f"(c[3])
                 : "r"(a[0]), "r"(a[1]), "r"(a[2]), "r"(a[3]), "r"(b[0]), "r"(b[1]));
}

/* ------------------------------------------------------------------ */
/* Kernel 1: f = relu(x @ w2 + b2) -> g_fpad (bf16, 98x98, zero borders) */
/* ------------------------------------------------------------------ */
__global__ void __launch_bounds__(256)
k1_f(const float* __restrict__ x, const float* __restrict__ w2,
     const float* __restrict__ b2)
{
    __shared__ float w2s[CH*CH];
    __shared__ float b2s[CH];
    int tid = threadIdx.x;
    for (int i = tid; i < CH*CH; i += 256) w2s[i] = w2[i];
    if (tid < CH) b2s[tid] = b2[tid];
    __syncthreads();

    int p = blockIdx.x * 256 + tid;
    if (p >= BB_*PPIX) return;
    int b  = p / PPIX;
    int r  = p % PPIX;
    int py = r / PW, px = r % PW;

    uint4* fr = (uint4*)(g_fpad + (size_t)p * CH);

    if (py == 0 || py == PW-1 || px == 0 || px == PW-1) {
        uint4 z = make_uint4(0,0,0,0);
        fr[0] = z; fr[1] = z; fr[2] = z; fr[3] = z;
        return;
    }
    int y = py - 1, xx = px - 1;

    uint64_t acc[CH/2];
    const uint64_t* b2p = (const uint64_t*)b2s;
#pragma unroll
    for (int j = 0; j < CH/2; j++) acc[j] = b2p[j];

    const float4* xp = (const float4*)(x + ((size_t)(b*HH + y)*WW + xx)*CH);
    const ulonglong2* w2v = (const ulonglong2*)w2s;
#pragma unroll 2
    for (int c4 = 0; c4 < CH/4; c4++) {
        float4 v = xp[c4];
        float vv[4] = {v.x, v.y, v.z, v.w};
#pragma unroll
        for (int k = 0; k < 4; k++) {
            uint64_t hv = pack2(vv[k]);
            int c = c4*4 + k;
#pragma unroll
            for (int j = 0; j < 8; j++) {
                ulonglong2 w = w2v[c*8 + j];
                ffma2(acc[2*j+0], hv, w.x);
                ffma2(acc[2*j+1], hv, w.y);
            }
        }
    }

    float s = 0.f;
    uint32_t pk[16];
#pragma unroll
    for (int j = 0; j < CH/2; j++) {
        float2 a = unpack2(acc[j]);
        float f0 = fmaxf(a.x, 0.f);
        float f1 = fmaxf(a.y, 0.f);
        s += f0 + f1;
        pk[j] = pk_bf16x2(f0, f1);
    }
    fr[0] = make_uint4(pk[0],  pk[1],  pk[2],  pk[3]);
    fr[1] = make_uint4(pk[4],  pk[5],  pk[6],  pk[7]);
    fr[2] = make_uint4(pk[8],  pk[9],  pk[10], pk[11]);
    fr[3] = make_uint4(pk[12], pk[13], pk[14], pk[15]);
    g_fsum[b*HWPIX + y*WW + xx] = s;
}

/* ------------------------------------------------------------------ */
/* Kernel 2: per (keypoint n, batch b, 8-row slab) — mma.sync          */
/* tap-FULLY-UNROLLED stage B, 2 passes x 3 strips/warp, fsum prefetch */
/* ------------------------------------------------------------------ */
__global__ void __launch_bounds__(256, 2)
k2_main(const float* __restrict__ wa, const float* __restrict__ ba,
        const float* __restrict__ wb, const float* __restrict__ bb,
        const float* __restrict__ Wp, float* __restrict__ out)
{
    extern __shared__ unsigned char smc[];
    uint32_t sb = smem_u32(smc);

    int tid  = threadIdx.x;
    int wid  = tid >> 5;
    int lane = tid & 31;
    int qid  = lane & 3;
    int row4 = lane >> 2;

    int n   = blockIdx.y / BB_;
    int b   = blockIdx.y % BB_;
    int y0p = blockIdx.x * SLABH;

    /* ---- stage smem ---- */
    {
        const uint4* fsrc = (const uint4*)(g_fpad + ((size_t)b*PPIX + (size_t)y0p*PW) * CH);
        for (int i = tid; i < HALON*4; i += 256) {
            int px = i >> 2, pt = i & 3;
            *(uint4*)(smc + SM_FH + (px+1)*RSTRIDE + pt*16) = fsrc[i];
        }
        if (tid < 65) {
            int s5 = tid / 5, pt = tid % 5;
            int slot = (s5 == 0) ? 0 : (980 + s5);
            *(uint4*)(smc + SM_FH + slot*RSTRIDE + pt*16) = make_uint4(0,0,0,0);
        }
    }
    {
        uint16_t* was = (uint16_t*)(smc + SM_WA);
        for (int i = tid; i < CH*CH; i += 256) {
            int d = i >> 5, c = i & 31;
            __nv_bfloat16 v = __float2bfloat16(wa[n*CH*CH + c*CH + d]);
            was[d*40 + c] = *(uint16_t*)&v;
        }
        uint16_t* wbs = (uint16_t*)(smc + SM_WB);
        for (int i = tid; i < 9*CH*CH; i += 256) {
            int t = i >> 10, r = i & 1023;
            int d = r >> 5, c = r & 31;
            __nv_bfloat16 v = __float2bfloat16(wb[(size_t)n*9*CH*CH + t*CH*CH + c*CH + d]);
            wbs[t*1280 + d*40 + c] = *(uint16_t*)&v;
        }
    }
    if (tid < CH) {
        ((float*)(smc + SM_BA))[tid] = ba[n*CH + tid];
        ((float*)(smc + SM_BB))[tid] = bb[n*CH + tid];
        float s = 0.f;
        const float* wpp = Wp + (n*CH + tid)*CH;
#pragma unroll
        for (int o = 0; o < CH; o++) s += wpp[o];
        ((float*)(smc + SM_WP))[tid] = s;
    }
    __syncthreads();

    uint32_t aoffA  = (uint32_t)(lane & 15) * RSTRIDE + (uint32_t)(lane >> 4) * 16;
    uint32_t aoffB4 = (uint32_t)(lane & 7)  * RSTRIDE + (uint32_t)(lane >> 3) * 16;

    /* ---- stage A: h = relu(f @ wa + ba), in-place over f ---- */
    {
        uint32_t bwa[16];
#pragma unroll
        for (int nb = 0; nb < 4; nb++)
            ldsm_x4(bwa + nb*4, sb + SM_WA + nb*8*RSTRIDE + aoffB4);
        float ba_r[8];
        const float* ba_s = (const float*)(smc + SM_BA);
#pragma unroll
        for (int nb = 0; nb < 4; nb++) {
            ba_r[nb*2+0] = ba_s[nb*8 + qid*2 + 0];
            ba_r[nb*2+1] = ba_s[nb*8 + qid*2 + 1];
        }

        for (int st = wid; st < NST_A; st += 8) {
            int P = st * 16;
            uint32_t abase = sb + SM_FH + (uint32_t)(P+1)*RSTRIDE;
            uint32_t A0[4], A1[4];
            ldsm_x4(A0, abase + aoffA);
            ldsm_x4(A1, abase + 32 + aoffA);

            float acc[16];
#pragma unroll
            for (int i = 0; i < 16; i++) acc[i] = 0.f;
#pragma unroll
            for (int nb = 0; nb < 4; nb++) {
                mma16816(acc + nb*4, A0, bwa + nb*4);
                mma16816(acc + nb*4, A1, bwa + nb*4 + 2);
            }

            int p0 = P + row4, p1 = p0 + 8;
            int px0 = p0 % PW, py0 = y0p + p0 / PW;
            int px1 = p1 % PW, py1 = y0p + p1 / PW;
            bool v0 = (p0 < HALON) && (px0 >= 1) && (px0 <= WW) && (py0 >= 1) && (py0 <= HH);
            bool v1 = (p1 < HALON) && (px1 >= 1) && (px1 <= WW) && (py1 >= 1) && (py1 <= HH);
#pragma unroll
            for (int nb = 0; nb < 4; nb++) {
                float e0 = v0 ? fmaxf(acc[nb*4+0] + ba_r[nb*2+0], 0.f) : 0.f;
                float e1 = v0 ? fmaxf(acc[nb*4+1] + ba_r[nb*2+1], 0.f) : 0.f;
                float e2 = v1 ? fmaxf(acc[nb*4+2] + ba_r[nb*2+0], 0.f) : 0.f;
                float e3 = v1 ? fmaxf(acc[nb*4+3] + ba_r[nb*2+1], 0.f) : 0.f;
                *(uint32_t*)(smc + SM_FH + (p0+1)*RSTRIDE + nb*16 + qid*4) = pk_bf16x2(e0, e1);
                *(uint32_t*)(smc + SM_FH + (p1+1)*RSTRIDE + nb*16 + qid*4) = pk_bf16x2(e2, e3);
            }
        }
    }
    __syncthreads();

    /* ---- stage B: 2 passes x (taps fully unrolled, 3 strips/warp) ---- */
    {
        float bb_r[8], wp_r[8];
        const float* bb_s = (const float*)(smc + SM_BB);
        const float* wp_s = (const float*)(smc + SM_WP);
#pragma unroll
        for (int nb = 0; nb < 4; nb++) {
            bb_r[nb*2+0] = bb_s[nb*8 + qid*2 + 0];
            bb_r[nb*2+1] = bb_s[nb*8 + qid*2 + 1];
            wp_r[nb*2+0] = wp_s[nb*8 + qid*2 + 0];
            wp_r[nb*2+1] = wp_s[nb*8 + qid*2 + 1];
        }

#pragma unroll 1
        for (int g = 0; g < 2; g++) {
            /* strips: wid + g*8 + {0,16,32}  -> covers 0..47 over both passes */
            float acc[3][16];
#pragma unroll
            for (int k = 0; k < 3; k++)
#pragma unroll
                for (int i = 0; i < 16; i++) acc[k][i] = 0.f;

            /* prefetch fsum for this pass's 6 output rows */
            float fpre[3][2];
#pragma unroll
            for (int k = 0; k < 3; k++) {
                int P = PW + (wid + g*8 + k*16) * 16;
                int p0 = P + row4, p1 = p0 + 8;
                int hx0 = p0 % PW, hy0 = p0 / PW;
                int hx1 = p1 % PW, hy1 = p1 / PW;
                fpre[k][0] = (hx0 >= 1 && hx0 <= WW)
                    ? g_fsum[(b*HH + (y0p + hy0 - 1))*WW + (hx0 - 1)] : 0.f;
                fpre[k][1] = (hx1 >= 1 && hx1 <= WW)
                    ? g_fsum[(b*HH + (y0p + hy1 - 1))*WW + (hx1 - 1)] : 0.f;
            }

#pragma unroll
            for (int tap = 0; tap < 9; tap++) {
                const int s = (tap/3 - 1)*PW + (tap%3 - 1);
                uint32_t wbase = sb + SM_WB + tap*2560;
                uint32_t bw[16];
#pragma unroll
                for (int nb = 0; nb < 4; nb++)
                    ldsm_x4(bw + nb*4, wbase + nb*8*RSTRIDE + aoffB4);

#pragma unroll
                for (int k = 0; k < 3; k++) {
                    int P = PW + (wid + g*8 + k*16) * 16;
                    uint32_t abase = sb + SM_FH + (uint32_t)(P + s + 1)*RSTRIDE;
                    uint32_t A0[4], A1[4];
                    ldsm_x4(A0, abase + aoffA);
                    ldsm_x4(A1, abase + 32 + aoffA);
#pragma unroll
                    for (int nb = 0; nb < 4; nb++) {
                        mma16816(acc[k] + nb*4, A0, bw + nb*4);
                        mma16816(acc[k] + nb*4, A1, bw + nb*4 + 2);
                    }
                }
            }

#pragma unroll
            for (int k = 0; k < 3; k++) {
                int P = PW + (wid + g*8 + k*16) * 16;
                float l0 = 0.f, l1 = 0.f;
#pragma unroll
                for (int nb = 0; nb < 4; nb++) {
                    l0 += fmaxf(acc[k][nb*4+0] + bb_r[nb*2+0], 0.f) * wp_r[nb*2+0];
                    l0 += fmaxf(acc[k][nb*4+1] + bb_r[nb*2+1], 0.f) * wp_r[nb*2+1];
                    l1 += fmaxf(acc[k][nb*4+2] + bb_r[nb*2+0], 0.f) * wp_r[nb*2+0];
                    l1 += fmaxf(acc[k][nb*4+3] + bb_r[nb*2+1], 0.f) * wp_r[nb*2+1];
                }
                l0 += __shfl_xor_sync(0xffffffffu, l0, 1);
                l0 += __shfl_xor_sync(0xffffffffu, l0, 2);
                l1 += __shfl_xor_sync(0xffffffffu, l1, 1);
                l1 += __shfl_xor_sync(0xffffffffu, l1, 2);

                if (qid == 0) {
                    int p0 = P + row4;
                    int hx0 = p0 % PW, hy0 = p0 / PW;
                    if (hx0 >= 1 && hx0 <= WW) {
                        int idx = (b*HH + (y0p + hy0 - 1))*WW + (hx0 - 1);
                        out[(size_t)idx*NKP + n] = fpre[k][0] + l0;
                    }
                    int p1 = p0 + 8;
                    int hx1 = p1 % PW, hy1 = p1 / PW;
                    if (hx1 >= 1 && hx1 <= WW) {
                        int idx = (b*HH + (y0p + hy1 - 1))*WW + (hx1 - 1);
                        out[(size_t)idx*NKP + n] = fpre[k][1] + l1;
                    }
                }
            }
        }

        /* leftover strip 48 (warp 0 only) */
        if (wid == 0) {
            int P = PW + 48 * 16;
            float a4[16];
#pragma unroll
            for (int i = 0; i < 16; i++) a4[i] = 0.f;
#pragma unroll 1
            for (int tap = 0; tap < 9; tap++) {
                int s = (tap/3 - 1)*PW + (tap%3 - 1);
                uint32_t wbase = sb + SM_WB + tap*2560;
                uint32_t abase = sb + SM_FH + (uint32_t)(P + s + 1)*RSTRIDE;
                uint32_t A0[4], A1[4];
                ldsm_x4(A0, abase + aoffA);
                ldsm_x4(A1, abase + 32 + aoffA);
#pragma unroll
                for (int nb = 0; nb < 4; nb++) {
                    uint32_t bw4[4];
                    ldsm_x4(bw4, wbase + nb*8*RSTRIDE + aoffB4);
                    mma16816(a4 + nb*4, A0, bw4);
                    mma16816(a4 + nb*4, A1, bw4 + 2);
                }
            }
            float l0 = 0.f, l1 = 0.f;
#pragma unroll
            for (int nb = 0; nb < 4; nb++) {
                l0 += fmaxf(a4[nb*4+0] + bb_r[nb*2+0], 0.f) * wp_r[nb*2+0];
                l0 += fmaxf(a4[nb*4+1] + bb_r[nb*2+1], 0.f) * wp_r[nb*2+1];
                l1 += fmaxf(a4[nb*4+2] + bb_r[nb*2+0], 0.f) * wp_r[nb*2+0];
                l1 += fmaxf(a4[nb*4+3] + bb_r[nb*2+1], 0.f) * wp_r[nb*2+1];
            }
            l0 += __shfl_xor_sync(0xffffffffu, l0, 1);
            l0 += __shfl_xor_sync(0xffffffffu, l0, 2);
            l1 += __shfl_xor_sync(0xffffffffu, l1, 1);
            l1 += __shfl_xor_sync(0xffffffffu, l1, 2);
            if (qid == 0) {
                int p0 = P + row4;
                int hx0 = p0 % PW, hy0 = p0 / PW;
                if (hx0 >= 1 && hx0 <= WW) {
                    int idx = (b*HH + (y0p + hy0 - 1))*WW + (hx0 - 1);
                    out[(size_t)idx*NKP + n] = g_fsum[idx] + l0;
                }
                int p1 = p0 + 8;
                int hx1 = p1 % PW, hy1 = p1 / PW;
                if (hx1 >= 1 && hx1 <= WW) {
                    int idx = (b*HH + (y0p + hy1 - 1))*WW + (hx1 - 1);
                    out[(size_t)idx*NKP + n] = g_fsum[idx] + l1;
                }
            }
        }
    }
}

/* ------------------------------------------------------------------ */
extern "C" void kernel_launch(void* const* d_in, const int* in_sizes, int n_in,
                              void* d_out, int out_size)
{
    const float* x  = (const float*)d_in[0];
    const float* w2 = (const float*)d_in[1];
    const float* b2 = (const float*)d_in[2];
    const float* wa = (const float*)d_in[3];
    const float* ba = (const float*)d_in[4];
    const float* wb = (const float*)d_in[5];
    const float* bb = (const float*)d_in[6];
    const float* Wp = (const float*)d_in[7];
    float* out = (float*)d_out;

    k1_f<<<(BB_*PPIX + 255)/256, 256>>>(x, w2, b2);

    cudaFuncSetAttribute(k2_main, cudaFuncAttributeMaxDynamicSharedMemorySize, SMEM_SZ);
    dim3 grid(HH/SLABH, NKP*BB_);
    k2_main<<<grid, 256, SMEM_SZ>>>(wa, ba, wb, bb, Wp, out);
}